// round 11
// baseline (speedup 1.0000x reference)
#include <cuda_runtime.h>
#include <cuda_fp16.h>
#include <math.h>
#include <stdint.h>

#define NB   32
#define SEQL 512
#define DIM  256
#define S2   514
#define NTOK (NB * S2)
#define HID  1024
#define WD   1280
#define NSTEPS 6
#define EPSF 1e-9f

// single-plane fp16 activation buffers (GEMM operands)
static __device__ __align__(256) __half g_flat[NTOK * WD];
static __device__ __align__(256) __half g_cc[NTOK * 2 * DIM];
static __device__ __align__(256) __half g_inter[NTOK * HID];
static __device__ __align__(256) float g_contents[NTOK * HID];
static __device__ __align__(256) float g_convOut[NTOK * DIM];   // init path only
static __device__ __align__(256) float g_seq[NTOK * DIM];       // fp32 state (exact blend path)
static __device__ float g_tsc[NTOK], g_tp[NTOK], g_ltp[NTOK];
static __device__ float g_active[NTOK], g_mask[NTOK], g_selp[NTOK], g_endm[NTOK];
static __device__ float g_mx;
// pre-transposed fp16 weights: Wt[n*K+k] = fp16(W[k*N+n])
static __device__ __align__(256) __half g_convWt[DIM * WD];
static __device__ __align__(256) __half g_w1Wt[HID * 2 * DIM];
static __device__ __align__(256) __half g_w2Wt[HID * HID];
static __device__ __align__(256) __half g_itWt[DIM * DIM];

__device__ __forceinline__ float geluf(float x) {
    float x3 = x * x * x;
    return 0.5f * x * (1.f + tanhf(0.7978845608028654f * (x + 0.044715f * x3)));
}
__device__ __forceinline__ void st4h(__half* H, float4 v) {
    ushort4 h;
    h.x = __half_as_ushort(__float2half_rn(v.x));
    h.y = __half_as_ushort(__float2half_rn(v.y));
    h.z = __half_as_ushort(__float2half_rn(v.z));
    h.w = __half_as_ushort(__float2half_rn(v.w));
    *(ushort4*)H = h;
}

__device__ __forceinline__ float blockReduceSum256(float v) {
    __shared__ float sh[33];
    int lane = threadIdx.x & 31, wid = threadIdx.x >> 5;
#pragma unroll
    for (int o = 16; o; o >>= 1) v += __shfl_down_sync(0xffffffffu, v, o);
    __syncthreads();
    if (lane == 0) sh[wid] = v;
    __syncthreads();
    if (wid == 0) {
        float t = (lane < 8) ? sh[lane] : 0.f;
#pragma unroll
        for (int o = 16; o; o >>= 1) t += __shfl_down_sync(0xffffffffu, t, o);
        if (lane == 0) sh[32] = t;
    }
    __syncthreads();
    return sh[32];
}

// ---------------- mma.sync helpers ----------------
__device__ __forceinline__ uint32_t s2u(const void* p) { return (uint32_t)__cvta_generic_to_shared(p); }
__device__ __forceinline__ void ldm4(uint32_t* r, uint32_t a) {
    asm volatile("ldmatrix.sync.aligned.m8n8.x4.shared.b16 {%0,%1,%2,%3}, [%4];"
                 : "=r"(r[0]), "=r"(r[1]), "=r"(r[2]), "=r"(r[3]) : "r"(a));
}
// f16-accumulate MMA with C = 0: D(f16x2 pair) = A*B
__device__ __forceinline__ void mma16816h(uint32_t* d, const uint32_t* a, const uint32_t* b) {
    asm volatile("mma.sync.aligned.m16n8k16.row.col.f16.f16.f16.f16 "
                 "{%0,%1},{%2,%3,%4,%5},{%6,%7},{%8,%8};"
                 : "=r"(d[0]), "=r"(d[1])
                 : "r"(a[0]), "r"(a[1]), "r"(a[2]), "r"(a[3]),
                   "r"(b[0]), "r"(b[1]), "r"(0u));
}
__device__ __forceinline__ void cpasync16(uint32_t dst, const void* src, int srcsize) {
    asm volatile("cp.async.cg.shared.global [%0], [%1], 16, %2;"
                 :: "r"(dst), "l"(src), "r"(srcsize) : "memory");
}

// ---------------- GEMM: C[M,N] = A@B^T + bias (fp16, f16-acc per k16, f32 master) ------
// CTA 128x256, 512 threads (16 warps of 64x32), K-tile 64, 2-stage cp.async.
// SMEM stage (55296B): A[128x144] B[+18432, 256x144]
// SCORE=1: no C store; epilogue computes tsc[row] = gelu(row)·scW + scb, atomicMax g_mx.
#define STG_BYTES 55296
#define ROWB 144
template <int ACT, int OUTP, int SCORE>
__global__ __launch_bounds__(512, 1) void mma_gemm(
    const __half* __restrict__ A, int lda,
    const __half* __restrict__ B,
    const float* __restrict__ bias, void* __restrict__ C0,
    int ldc, int M, int K,
    const float* __restrict__ scW, const float* __restrict__ scb)
{
    extern __shared__ char smem[];
    const uint32_t sbase = s2u(smem);
    const int tid = threadIdx.x, w = tid >> 5, lane = tid & 31;
    const int bm = blockIdx.y * 128, bn = blockIdx.x * 256;
    const int NK = K >> 6;
    const int m0 = (w & 1) * 64, n0w = (w >> 1) * 32;

    float acc[4][4][4];
#pragma unroll
    for (int i = 0; i < 4; i++)
#pragma unroll
        for (int j = 0; j < 4; j++)
#pragma unroll
            for (int e = 0; e < 4; e++) acc[i][j][e] = 0.f;

    auto fill = [&](int st, int kt) {
        int k0 = kt << 6;
#pragma unroll
        for (int q = 0; q < 6; q++) {
            int u = tid + q * 512;               // 3072 units of 16B
            const __half* src;
            uint32_t dst;
            int sz = 16;
            if (u < 1024) {
                int r = u >> 3, c = u & 7;
                int gr = bm + r;
                if (gr >= M) { gr = 0; sz = 0; }
                src = A + (size_t)gr * lda + k0 + c * 8;
                dst = sbase + st * STG_BYTES + r * ROWB + c * 16;
            } else {
                int v = u - 1024;
                int r = (v >> 3) & 255, c = v & 7;
                src = B + (size_t)(bn + r) * K + k0 + c * 8;
                dst = sbase + st * STG_BYTES + 18432 + r * ROWB + c * 16;
            }
            cpasync16(dst, src, sz);
        }
        asm volatile("cp.async.commit_group;" ::: "memory");
    };

    fill(0, 0);
    for (int kt = 0; kt < NK; kt++) {
        if (kt + 1 < NK) {
            fill((kt + 1) & 1, kt + 1);
            asm volatile("cp.async.wait_group 1;" ::: "memory");
        } else {
            asm volatile("cp.async.wait_group 0;" ::: "memory");
        }
        __syncthreads();

        const uint32_t sA = sbase + (kt & 1) * STG_BYTES;
        const uint32_t sB = sA + 18432;
#pragma unroll
        for (int kh = 0; kh < 4; kh++) {
            uint32_t a[4][4], bfr[2][4];
            int aoff = (m0 + (lane & 15)) * ROWB + kh * 32 + (lane >> 4) * 16;
            int boff = (n0w + ((lane & 7) | ((lane >> 1) & 8))) * ROWB
                       + kh * 32 + ((lane >> 3) & 1) * 16;
#pragma unroll
            for (int nt = 0; nt < 2; nt++)
                ldm4(bfr[nt], sB + boff + nt * 16 * ROWB);
#pragma unroll
            for (int mi = 0; mi < 4; mi++) ldm4(a[mi], sA + aoff + mi * 16 * ROWB);
            // f16-acc MMA (C=0), immediate fp32 flush (one f16 rounding per k16 block)
#pragma unroll
            for (int mi = 0; mi < 4; mi++) {
                uint32_t dh[4][2];
#pragma unroll
                for (int fi = 0; fi < 4; fi++)
                    mma16816h(dh[fi], a[mi], &bfr[fi >> 1][(fi & 1) * 2]);
#pragma unroll
                for (int fi = 0; fi < 4; fi++) {
                    float2 f0 = __half22float2(*(__half2*)&dh[fi][0]);
                    float2 f1 = __half22float2(*(__half2*)&dh[fi][1]);
                    acc[mi][fi][0] += f0.x; acc[mi][fi][1] += f0.y;
                    acc[mi][fi][2] += f1.x; acc[mi][fi][3] += f1.y;
                }
            }
        }
        __syncthreads();
    }

    // epilogue
    int tq = lane >> 2, tr = lane & 3;
    if (SCORE) {
        float* srow = (float*)smem;
        if (tid < 128) srow[tid] = 0.f;
        __syncthreads();
#pragma unroll
        for (int mi = 0; mi < 4; mi++)
#pragma unroll
            for (int half = 0; half < 2; half++) {
                int rl = m0 + mi * 16 + tq + half * 8;
                float s = 0.f;
#pragma unroll
                for (int fi = 0; fi < 4; fi++) {
                    int col = bn + n0w + fi * 8 + tr * 2;
                    float v0 = geluf(acc[mi][fi][half * 2 + 0] + bias[col]);
                    float v1 = geluf(acc[mi][fi][half * 2 + 1] + bias[col + 1]);
                    s += v0 * scW[col] + v1 * scW[col + 1];
                }
                atomicAdd(&srow[rl], s);
            }
        __syncthreads();
        if (tid < 128) {
            int gr = bm + tid;
            if (gr < M) {
                float t = srow[tid] + scb[0];
                g_tsc[gr] = t;
                atomicMax((unsigned int*)&g_mx, __float_as_uint(fmaxf(t, 0.f)));
            }
        }
        return;
    }
#pragma unroll
    for (int mi = 0; mi < 4; mi++) {
#pragma unroll
        for (int fi = 0; fi < 4; fi++) {
            int col = bn + n0w + fi * 8 + tr * 2;
            float b0 = bias[col], b1 = bias[col + 1];
#pragma unroll
            for (int half = 0; half < 2; half++) {
                int row = bm + m0 + mi * 16 + tq + half * 8;
                if (row >= M) continue;
                float v0 = acc[mi][fi][half * 2 + 0] + b0;
                float v1 = acc[mi][fi][half * 2 + 1] + b1;
                if (ACT) { v0 = geluf(v0); v1 = geluf(v1); }
                if (OUTP) {
                    ushort2 h;
                    h.x = __half_as_ushort(__float2half_rn(v0));
                    h.y = __half_as_ushort(__float2half_rn(v1));
                    *(ushort2*)((__half*)C0 + (size_t)row * ldc + col) = h;
                } else {
                    *(float2*)((float*)C0 + (size_t)row * ldc + col) = make_float2(v0, v1);
                }
            }
        }
    }
}

// ---------------- init kernels ----------------
__global__ void init_masks_kernel(const float* __restrict__ im) {
    int idx = blockIdx.x * blockDim.x + threadIdx.x;
    if (idx == 0) g_mx = 0.f;
    if (idx >= NTOK) return;
    int b = idx / S2, i = idx % S2;
    auto mask_yes = [&](int j) -> float { return (j <= 1) ? 1.f : im[b * SEQL + (j - 2)]; };
    auto mask_no_end = [&](int j) -> float {
        if (j == 0) return 1.f;
        if (j <= SEQL) return im[b * SEQL + (j - 1)];
        return 0.f;
    };
    float my = mask_yes(i), mne = mask_no_end(i);
    float mask_no_start = (i == 0) ? 0.f : my;
    float last_token = (i < S2 - 1) ? (mask_yes(i + 1) - mask_no_end(i + 1)) : 0.f;
    g_mask[idx] = my;
    g_endm[idx] = my - mne;
    g_selp[idx] = mask_no_start * mne * (1.f - last_token);
    g_active[idx] = my;
    g_ltp[idx] = 0.f;
}

__global__ void init_seqpre_kernel(const float* __restrict__ seqin,
                                   const float* __restrict__ START,
                                   const float* __restrict__ END) {
    int idx = blockIdx.x * blockDim.x + threadIdx.x;
    if (idx >= NTOK * DIM) return;
    int tok = idx / DIM, f = idx % DIM;
    int b = tok / S2, i = tok % S2;
    float base;
    if (i == 0)          base = START[f];
    else if (i <= SEQL)  base = seqin[((size_t)b * SEQL + (i - 1)) * DIM + f];
    else                 base = 0.f;
    float e = g_endm[tok];
    float x = e * END[f] + (1.f - e) * base;
    g_cc[(size_t)tok * (2 * DIM) + f] = __float2half_rn(x);
}

__global__ void ln_init_kernel(const float* __restrict__ lng, const float* __restrict__ lnb) {
    int tok = blockIdx.x, f = threadIdx.x;
    float x = g_convOut[(size_t)tok * DIM + f];
    float mean = blockReduceSum256(x) * (1.f / DIM);
    float d = x - mean;
    float r = rsqrtf(blockReduceSum256(d * d) * (1.f / DIM) + 1e-5f);
    g_seq[(size_t)tok * DIM + f] = (d * r * lng[f] + lnb[f]) * g_mask[tok];
}

// merged pack: itW | convW | w1 | w2 (single launch -> mma_gemm is launch #4 for ncu)
__global__ void pack_all(const float* __restrict__ Wit, __half* __restrict__ Tit,
                         const float* __restrict__ Wcv, __half* __restrict__ Tcv,
                         const float* __restrict__ W1,  __half* __restrict__ T1,
                         const float* __restrict__ W2,  __half* __restrict__ T2) {
    int i = blockIdx.x * blockDim.x + threadIdx.x;
    const int n_it = DIM * DIM;            // Bt [N=256][K=256]
    const int n_cv = DIM * WD;             // Bt [N=256][K=1280]
    const int n_w1 = HID * 2 * DIM;        // Bt [N=1024][K=512]
    const int n_w2 = HID * HID;            // Bt [N=1024][K=1024]
    if (i < n_it) {
        int n = i / DIM, k = i % DIM;
        Tit[i] = __float2half_rn(Wit[(size_t)k * DIM + n]);
    } else if (i < n_it + n_cv) {
        int j = i - n_it;
        int n = j / WD, k = j % WD;
        Tcv[j] = __float2half_rn(Wcv[(size_t)k * DIM + n]);
    } else if (i < n_it + n_cv + n_w1) {
        int j = i - n_it - n_cv;
        int n = j / (2 * DIM), k = j % (2 * DIM);
        T1[j] = __float2half_rn(W1[(size_t)k * HID + n]);
    } else {
        int j = i - n_it - n_cv - n_w1;
        if (j >= n_w2) return;
        int n = j / HID, k = j % HID;
        T2[j] = __float2half_rn(W2[(size_t)k * HID + n]);
    }
}

// ---------------- merged scan kernel ----------------
__global__ void scan_kernel(const float* __restrict__ yes_t, const float* __restrict__ no_t) {
    int idx = blockIdx.x * blockDim.x + threadIdx.x;
    if (idx < NB * 64) {
        int b = idx >> 6, f0 = (idx & 63) << 2;
        float4 yf = *(const float4*)(yes_t + f0);
        float4 nf = *(const float4*)(no_t + f0);
        float4 l1 = {0,0,0,0}, l2 = {0,0,0,0}, lc = {0,0,0,0};
        for (int i = 0; i < S2; i++) {
            int tok = b * S2 + i;
            float a = g_active[tok], m = g_mask[tok], lt = g_ltp[tok];
            float w = a * m * m, c = 1.f - a * m + EPSF;
            float4 sv = *(const float4*)(g_seq + (size_t)tok * DIM + f0);
            float4 base;
            base.x = sv.x + lt * yf.x + (1.f - lt) * nf.x;
            base.y = sv.y + lt * yf.y + (1.f - lt) * nf.y;
            base.z = sv.z + lt * yf.z + (1.f - lt) * nf.z;
            base.w = sv.w + lt * yf.w + (1.f - lt) * nf.w;
            size_t fl = (size_t)tok * WD;
            st4h(g_flat + fl + 0 * DIM + f0, l2);
            st4h(g_flat + fl + 1 * DIM + f0, l1);
            size_t cp = (size_t)tok * 2 * DIM;
            st4h(g_cc + cp + f0,       lc);
            st4h(g_cc + cp + DIM + f0, sv);
            float4 nl2;
            nl2.x = w * l1.x + c * l2.x; nl2.y = w * l1.y + c * l2.y;
            nl2.z = w * l1.z + c * l2.z; nl2.w = w * l1.w + c * l2.w;
            l1.x = w * base.x + c * l1.x; l1.y = w * base.y + c * l1.y;
            l1.z = w * base.z + c * l1.z; l1.w = w * base.w + c * l1.w;
            lc.x = w * sv.x + c * lc.x; lc.y = w * sv.y + c * lc.y;
            lc.z = w * sv.z + c * lc.z; lc.w = w * sv.w + c * lc.w;
            l2 = nl2;
        }
    } else {
        int j = idx - NB * 64;
        if (j >= NB * 64) return;
        int b = j >> 6, f0 = (j & 63) << 2;
        float4 yf = *(const float4*)(yes_t + f0);
        float4 nf = *(const float4*)(no_t + f0);
        float4 r1 = {0,0,0,0}, r2 = {0,0,0,0};
        for (int i = S2 - 1; i >= 0; i--) {
            int tok = b * S2 + i;
            float a = g_active[tok], m = g_mask[tok], lt = g_ltp[tok];
            float w = a * m * m, c = 1.f - a * m + EPSF;
            float4 sv = *(const float4*)(g_seq + (size_t)tok * DIM + f0);
            float4 base;
            base.x = sv.x + lt * yf.x + (1.f - lt) * nf.x;
            base.y = sv.y + lt * yf.y + (1.f - lt) * nf.y;
            base.z = sv.z + lt * yf.z + (1.f - lt) * nf.z;
            base.w = sv.w + lt * yf.w + (1.f - lt) * nf.w;
            size_t fl = (size_t)tok * WD;
            st4h(g_flat + fl + 2 * DIM + f0, base);
            st4h(g_flat + fl + 3 * DIM + f0, r1);
            st4h(g_flat + fl + 4 * DIM + f0, r2);
            float4 nr2;
            nr2.x = w * r1.x + c * r2.x; nr2.y = w * r1.y + c * r2.y;
            nr2.z = w * r1.z + c * r2.z; nr2.w = w * r1.w + c * r2.w;
            r1.x = w * base.x + c * r1.x; r1.y = w * base.y + c * r1.y;
            r1.z = w * base.z + c * r1.z; r1.w = w * base.w + c * r1.w;
            r2 = nr2;
        }
    }
}

// ---------------- per-step kernels ----------------
// combine: sv read from fp32 g_seq (exact blend path); lc from fp16 cc
__global__ void combine_kernel(const float* __restrict__ lng, const float* __restrict__ lnb) {
    int tok = blockIdx.x, f = threadIdx.x;
    const float* ct = g_contents + (size_t)tok * HID;
    size_t cp = (size_t)tok * 2 * DIM;
    float lc = __half2float(g_cc[cp + f]);
    float sv = g_seq[(size_t)tok * DIM + f];
    float g0 = 1.f / (1.f + expf(-ct[0 * DIM + f]));
    float g1 = 1.f / (1.f + expf(-ct[1 * DIM + f]));
    float g2 = 1.f / (1.f + expf(-ct[2 * DIM + f]));
    float y = g0 * lc + g1 * sv + g2 * ct[3 * DIM + f];
    float mean = blockReduceSum256(y) * (1.f / DIM);
    float d = y - mean;
    float r = rsqrtf(blockReduceSum256(d * d) * (1.f / DIM) + 1e-5f);
    float comp = d * r * lng[f] + lnb[f];
    float mx = g_mx;
    float et = expf(g_tsc[tok] - mx) * g_selp[tok];
    float tp = et / (et + expf(-mx) + EPSF);
    if (f == 0) g_tp[tok] = tp;
    g_seq[(size_t)tok * DIM + f] = (tp * comp + (1.f - tp) * sv) * g_mask[tok];
}

__global__ void deact_kernel() {
    __shared__ float s_a[S2], s_m[S2], s_tp[S2];
    int b = blockIdx.x;
    if (b == 0 && threadIdx.x == 0) g_mx = 0.f;   // reset for next step's score
    for (int i = threadIdx.x; i < S2; i += blockDim.x) {
        int tok = b * S2 + i;
        s_a[i] = g_active[tok]; s_m[i] = g_mask[tok]; s_tp[i] = g_tp[tok];
    }
    __syncthreads();
    if (threadIdx.x == 0) {
        float dacc = 0.f;
        for (int j = S2 - 1; j >= 0; j--) {
            float a = s_a[j], m = s_m[j], tp = s_tp[j];
            float de = a * m * m * dacc;
            s_a[j] = fminf(fmaxf(a * (1.f - de), 0.f), 1.f) * m;
            dacc = tp + (1.f - a * m + EPSF) * dacc;
        }
    }
    __syncthreads();
    for (int i = threadIdx.x; i < S2; i += blockDim.x) {
        int tok = b * S2 + i;
        g_active[tok] = s_a[i];
        g_ltp[tok]    = s_tp[i];
    }
}

__global__ void copy_out_kernel(float* __restrict__ out) {
    int idx = blockIdx.x * blockDim.x + threadIdx.x;
    if (idx < NTOK * DIM) out[idx] = g_seq[idx];
}

// ---------------- launch ----------------
extern "C" void kernel_launch(void* const* d_in, const int* in_sizes, int n_in,
                              void* d_out, int out_size) {
    const float* sequence   = (const float*)d_in[0];
    const float* input_mask = (const float*)d_in[1];
    const float* START = (const float*)d_in[2];
    const float* END   = (const float*)d_in[3];
    const float* yes_t = (const float*)d_in[4];
    const float* no_t  = (const float*)d_in[5];
    const float* convW = (const float*)d_in[6];
    const float* convb = (const float*)d_in[7];
    const float* scW   = (const float*)d_in[8];
    const float* scb   = (const float*)d_in[9];
    const float* itW   = (const float*)d_in[10];
    const float* itb   = (const float*)d_in[11];
    const float* w1W   = (const float*)d_in[12];
    const float* w1b   = (const float*)d_in[13];
    const float* w2W   = (const float*)d_in[14];
    const float* w2b   = (const float*)d_in[15];
    const float* lng   = (const float*)d_in[16];
    const float* lnb   = (const float*)d_in[17];
    float* out = (float*)d_out;

    __half *p_flat, *p_cc, *p_inter, *p_convWt, *p_w1Wt, *p_w2Wt, *p_itWt;
    float *p_contents, *p_convOut;
    cudaGetSymbolAddress((void**)&p_flat, g_flat);
    cudaGetSymbolAddress((void**)&p_cc, g_cc);
    cudaGetSymbolAddress((void**)&p_inter, g_inter);
    cudaGetSymbolAddress((void**)&p_contents, g_contents);
    cudaGetSymbolAddress((void**)&p_convOut, g_convOut);
    cudaGetSymbolAddress((void**)&p_convWt, g_convWt);
    cudaGetSymbolAddress((void**)&p_w1Wt, g_w1Wt);
    cudaGetSymbolAddress((void**)&p_w2Wt, g_w2Wt);
    cudaGetSymbolAddress((void**)&p_itWt, g_itWt);

    const int SMEMB = 2 * STG_BYTES;   // 110592
    cudaFuncSetAttribute(mma_gemm<0,0,0>, cudaFuncAttributeMaxDynamicSharedMemorySize, SMEMB);
    cudaFuncSetAttribute(mma_gemm<1,1,0>, cudaFuncAttributeMaxDynamicSharedMemorySize, SMEMB);
    cudaFuncSetAttribute(mma_gemm<1,0,1>, cudaFuncAttributeMaxDynamicSharedMemorySize, SMEMB);

    const int THR = 256;
    const int GM = (NTOK + 127) / 128;   // 129
    const int PACK_N = DIM * DIM + DIM * WD + HID * 2 * DIM + HID * HID;

    // launches 1-3, then mma_gemm is launch #4 (ncu-visible)
    init_masks_kernel<<<(NTOK + THR - 1) / THR, THR>>>(input_mask);
    init_seqpre_kernel<<<(NTOK * DIM + THR - 1) / THR, THR>>>(sequence, START, END);
    pack_all<<<(PACK_N + THR - 1) / THR, THR>>>(itW, p_itWt, convW, p_convWt,
                                                w1W, p_w1Wt, w2W, p_w2Wt);

    mma_gemm<0,0,0><<<dim3(1, GM), 512, SMEMB>>>(p_cc, 2 * DIM,
        p_itWt, itb, p_convOut, DIM, NTOK, DIM, nullptr, nullptr);
    ln_init_kernel<<<NTOK, DIM>>>(lng, lnb);

    for (int s = 0; s < NSTEPS; s++) {
        scan_kernel<<<(2 * NB * 64 + THR - 1) / THR, THR>>>(yes_t, no_t);
        mma_gemm<1,0,1><<<dim3(1, GM), 512, SMEMB>>>(p_flat, WD,
            p_convWt, convb, nullptr, DIM, NTOK, WD, scW, scb);
        mma_gemm<1,1,0><<<dim3(4, GM), 512, SMEMB>>>(p_cc, 2 * DIM,
            p_w1Wt, w1b, p_inter, HID, NTOK, 2 * DIM, nullptr, nullptr);
        mma_gemm<0,0,0><<<dim3(4, GM), 512, SMEMB>>>(p_inter, HID,
            p_w2Wt, w2b, p_contents, HID, NTOK, HID, nullptr, nullptr);
        combine_kernel<<<NTOK, DIM>>>(lng, lnb);
        deact_kernel<<<NB, 128>>>();
    }

    copy_out_kernel<<<(NTOK * DIM + THR - 1) / THR, THR>>>(out);
}

// round 12
// speedup vs baseline: 1.1576x; 1.1576x over previous
#include <cuda_runtime.h>
#include <cuda_fp16.h>
#include <math.h>
#include <stdint.h>

#define NB   32
#define SEQL 512
#define DIM  256
#define S2   514
#define NTOK (NB * S2)
#define HID  1024
#define WD   1280
#define NSTEPS 6
#define EPSF 1e-9f
#define NCH  8          // scan chunks per batch
#define CS   65         // chunk size (8*65 >= 514)

// single-plane fp16 activation buffers (GEMM operands)
static __device__ __align__(256) __half g_flat[NTOK * WD];
static __device__ __align__(256) __half g_cc[NTOK * 2 * DIM];
static __device__ __align__(256) __half g_inter[NTOK * HID];
static __device__ __align__(256) float g_contents[NTOK * HID];
static __device__ __align__(256) float g_convOut[NTOK * DIM];   // init path only
static __device__ __align__(256) float g_seq[NTOK * DIM];       // fp32 state
static __device__ __align__(256) float g_bnd[NB * NCH * 5 * DIM]; // scan boundary states
static __device__ float g_tsc[NTOK], g_tp[NTOK], g_ltp[NTOK];
static __device__ float g_active[NTOK], g_mask[NTOK], g_selp[NTOK], g_endm[NTOK];
static __device__ float g_mx;
// pre-transposed fp16 weights: Wt[n*K+k] = fp16(W[k*N+n])
static __device__ __align__(256) __half g_convWt[DIM * WD];
static __device__ __align__(256) __half g_w1Wt[HID * 2 * DIM];
static __device__ __align__(256) __half g_w2Wt[HID * HID];
static __device__ __align__(256) __half g_itWt[DIM * DIM];

__device__ __forceinline__ float geluf(float x) {
    float x3 = x * x * x;
    return 0.5f * x * (1.f + tanhf(0.7978845608028654f * (x + 0.044715f * x3)));
}
__device__ __forceinline__ void st4h(__half* H, float4 v) {
    ushort4 h;
    h.x = __half_as_ushort(__float2half_rn(v.x));
    h.y = __half_as_ushort(__float2half_rn(v.y));
    h.z = __half_as_ushort(__float2half_rn(v.z));
    h.w = __half_as_ushort(__float2half_rn(v.w));
    *(ushort4*)H = h;
}

__device__ __forceinline__ float blockReduceSum256(float v) {
    __shared__ float sh[33];
    int lane = threadIdx.x & 31, wid = threadIdx.x >> 5;
#pragma unroll
    for (int o = 16; o; o >>= 1) v += __shfl_down_sync(0xffffffffu, v, o);
    __syncthreads();
    if (lane == 0) sh[wid] = v;
    __syncthreads();
    if (wid == 0) {
        float t = (lane < 8) ? sh[lane] : 0.f;
#pragma unroll
        for (int o = 16; o; o >>= 1) t += __shfl_down_sync(0xffffffffu, t, o);
        if (lane == 0) sh[32] = t;
    }
    __syncthreads();
    return sh[32];
}

// ---------------- mma.sync helpers ----------------
__device__ __forceinline__ uint32_t s2u(const void* p) { return (uint32_t)__cvta_generic_to_shared(p); }
__device__ __forceinline__ void ldm4(uint32_t* r, uint32_t a) {
    asm volatile("ldmatrix.sync.aligned.m8n8.x4.shared.b16 {%0,%1,%2,%3}, [%4];"
                 : "=r"(r[0]), "=r"(r[1]), "=r"(r[2]), "=r"(r[3]) : "r"(a));
}
__device__ __forceinline__ void mma16816(float* c, const uint32_t* a, const uint32_t* b) {
    asm volatile("mma.sync.aligned.m16n8k16.row.col.f32.f16.f16.f32 "
                 "{%0,%1,%2,%3},{%4,%5,%6,%7},{%8,%9},{%0,%1,%2,%3};"
                 : "+f"(c[0]), "+f"(c[1]), "+f"(c[2]), "+f"(c[3])
                 : "r"(a[0]), "r"(a[1]), "r"(a[2]), "r"(a[3]), "r"(b[0]), "r"(b[1]));
}
__device__ __forceinline__ void cpasync16(uint32_t dst, const void* src, int srcsize) {
    asm volatile("cp.async.cg.shared.global [%0], [%1], 16, %2;"
                 :: "r"(dst), "l"(src), "r"(srcsize) : "memory");
}

// ---------------- GEMM: C[M,N] = A@B^T + bias (plain fp16, f32 acc) ----------------
#define STG_BYTES 55296
#define ROWB 144
template <int ACT, int OUTP, int SCORE>
__global__ __launch_bounds__(512, 1) void mma_gemm(
    const __half* __restrict__ A, int lda,
    const __half* __restrict__ B,
    const float* __restrict__ bias, void* __restrict__ C0,
    int ldc, int M, int K,
    const float* __restrict__ scW, const float* __restrict__ scb)
{
    extern __shared__ char smem[];
    const uint32_t sbase = s2u(smem);
    const int tid = threadIdx.x, w = tid >> 5, lane = tid & 31;
    const int bm = blockIdx.y * 128, bn = blockIdx.x * 256;
    const int NK = K >> 6;
    const int m0 = (w & 1) * 64, n0w = (w >> 1) * 32;

    float acc[4][4][4];
#pragma unroll
    for (int i = 0; i < 4; i++)
#pragma unroll
        for (int j = 0; j < 4; j++)
#pragma unroll
            for (int e = 0; e < 4; e++) acc[i][j][e] = 0.f;

    auto fill = [&](int st, int kt) {
        int k0 = kt << 6;
#pragma unroll
        for (int q = 0; q < 6; q++) {
            int u = tid + q * 512;
            const __half* src;
            uint32_t dst;
            int sz = 16;
            if (u < 1024) {
                int r = u >> 3, c = u & 7;
                int gr = bm + r;
                if (gr >= M) { gr = 0; sz = 0; }
                src = A + (size_t)gr * lda + k0 + c * 8;
                dst = sbase + st * STG_BYTES + r * ROWB + c * 16;
            } else {
                int v = u - 1024;
                int r = (v >> 3) & 255, c = v & 7;
                src = B + (size_t)(bn + r) * K + k0 + c * 8;
                dst = sbase + st * STG_BYTES + 18432 + r * ROWB + c * 16;
            }
            cpasync16(dst, src, sz);
        }
        asm volatile("cp.async.commit_group;" ::: "memory");
    };

    fill(0, 0);
    for (int kt = 0; kt < NK; kt++) {
        if (kt + 1 < NK) {
            fill((kt + 1) & 1, kt + 1);
            asm volatile("cp.async.wait_group 1;" ::: "memory");
        } else {
            asm volatile("cp.async.wait_group 0;" ::: "memory");
        }
        __syncthreads();

        const uint32_t sA = sbase + (kt & 1) * STG_BYTES;
        const uint32_t sB = sA + 18432;
#pragma unroll
        for (int kh = 0; kh < 4; kh++) {
            uint32_t a[4][4], bfr[2][4];
            int aoff = (m0 + (lane & 15)) * ROWB + kh * 32 + (lane >> 4) * 16;
            int boff = (n0w + ((lane & 7) | ((lane >> 1) & 8))) * ROWB
                       + kh * 32 + ((lane >> 3) & 1) * 16;
#pragma unroll
            for (int nt = 0; nt < 2; nt++)
                ldm4(bfr[nt], sB + boff + nt * 16 * ROWB);
#pragma unroll
            for (int mi = 0; mi < 4; mi++) ldm4(a[mi], sA + aoff + mi * 16 * ROWB);
#pragma unroll
            for (int mi = 0; mi < 4; mi++)
#pragma unroll
                for (int fi = 0; fi < 4; fi++)
                    mma16816(acc[mi][fi], a[mi], &bfr[fi >> 1][(fi & 1) * 2]);
        }
        __syncthreads();
    }

    int tq = lane >> 2, tr = lane & 3;
    if (SCORE) {
        float* srow = (float*)smem;
        if (tid < 128) srow[tid] = 0.f;
        __syncthreads();
#pragma unroll
        for (int mi = 0; mi < 4; mi++)
#pragma unroll
            for (int half = 0; half < 2; half++) {
                int rl = m0 + mi * 16 + tq + half * 8;
                float s = 0.f;
#pragma unroll
                for (int fi = 0; fi < 4; fi++) {
                    int col = bn + n0w + fi * 8 + tr * 2;
                    float v0 = geluf(acc[mi][fi][half * 2 + 0] + bias[col]);
                    float v1 = geluf(acc[mi][fi][half * 2 + 1] + bias[col + 1]);
                    s += v0 * scW[col] + v1 * scW[col + 1];
                }
                atomicAdd(&srow[rl], s);
            }
        __syncthreads();
        if (tid < 128) {
            int gr = bm + tid;
            if (gr < M) {
                float t = srow[tid] + scb[0];
                g_tsc[gr] = t;
                atomicMax((unsigned int*)&g_mx, __float_as_uint(fmaxf(t, 0.f)));
            }
        }
        return;
    }
#pragma unroll
    for (int mi = 0; mi < 4; mi++) {
#pragma unroll
        for (int fi = 0; fi < 4; fi++) {
            int col = bn + n0w + fi * 8 + tr * 2;
            float b0 = bias[col], b1 = bias[col + 1];
#pragma unroll
            for (int half = 0; half < 2; half++) {
                int row = bm + m0 + mi * 16 + tq + half * 8;
                if (row >= M) continue;
                float v0 = acc[mi][fi][half * 2 + 0] + b0;
                float v1 = acc[mi][fi][half * 2 + 1] + b1;
                if (ACT) { v0 = geluf(v0); v1 = geluf(v1); }
                if (OUTP) {
                    ushort2 h;
                    h.x = __half_as_ushort(__float2half_rn(v0));
                    h.y = __half_as_ushort(__float2half_rn(v1));
                    *(ushort2*)((__half*)C0 + (size_t)row * ldc + col) = h;
                } else {
                    *(float2*)((float*)C0 + (size_t)row * ldc + col) = make_float2(v0, v1);
                }
            }
        }
    }
}

// ---------------- init kernels ----------------
__global__ void init_masks_kernel(const float* __restrict__ im) {
    int idx = blockIdx.x * blockDim.x + threadIdx.x;
    if (idx == 0) g_mx = 0.f;
    if (idx >= NTOK) return;
    int b = idx / S2, i = idx % S2;
    auto mask_yes = [&](int j) -> float { return (j <= 1) ? 1.f : im[b * SEQL + (j - 2)]; };
    auto mask_no_end = [&](int j) -> float {
        if (j == 0) return 1.f;
        if (j <= SEQL) return im[b * SEQL + (j - 1)];
        return 0.f;
    };
    float my = mask_yes(i), mne = mask_no_end(i);
    float mask_no_start = (i == 0) ? 0.f : my;
    float last_token = (i < S2 - 1) ? (mask_yes(i + 1) - mask_no_end(i + 1)) : 0.f;
    g_mask[idx] = my;
    g_endm[idx] = my - mne;
    g_selp[idx] = mask_no_start * mne * (1.f - last_token);
    g_active[idx] = my;
    g_ltp[idx] = 0.f;
}

__global__ void init_seqpre_kernel(const float* __restrict__ seqin,
                                   const float* __restrict__ START,
                                   const float* __restrict__ END) {
    int idx = blockIdx.x * blockDim.x + threadIdx.x;
    if (idx >= NTOK * DIM) return;
    int tok = idx / DIM, f = idx % DIM;
    int b = tok / S2, i = tok % S2;
    float base;
    if (i == 0)          base = START[f];
    else if (i <= SEQL)  base = seqin[((size_t)b * SEQL + (i - 1)) * DIM + f];
    else                 base = 0.f;
    float e = g_endm[tok];
    float x = e * END[f] + (1.f - e) * base;
    g_cc[(size_t)tok * (2 * DIM) + f] = __float2half_rn(x);
}

__global__ void ln_init_kernel(const float* __restrict__ lng, const float* __restrict__ lnb) {
    int tok = blockIdx.x, f = threadIdx.x;
    float x = g_convOut[(size_t)tok * DIM + f];
    float mean = blockReduceSum256(x) * (1.f / DIM);
    float d = x - mean;
    float r = rsqrtf(blockReduceSum256(d * d) * (1.f / DIM) + 1e-5f);
    g_seq[(size_t)tok * DIM + f] = (d * r * lng[f] + lnb[f]) * g_mask[tok];
}

// merged pack: itW | convW | w1 | w2
__global__ void pack_all(const float* __restrict__ Wit, __half* __restrict__ Tit,
                         const float* __restrict__ Wcv, __half* __restrict__ Tcv,
                         const float* __restrict__ W1,  __half* __restrict__ T1,
                         const float* __restrict__ W2,  __half* __restrict__ T2) {
    int i = blockIdx.x * blockDim.x + threadIdx.x;
    const int n_it = DIM * DIM;
    const int n_cv = DIM * WD;
    const int n_w1 = HID * 2 * DIM;
    const int n_w2 = HID * HID;
    if (i < n_it) {
        int n = i / DIM, k = i % DIM;
        Tit[i] = __float2half_rn(Wit[(size_t)k * DIM + n]);
    } else if (i < n_it + n_cv) {
        int j = i - n_it;
        int n = j / WD, k = j % WD;
        Tcv[j] = __float2half_rn(Wcv[(size_t)k * DIM + n]);
    } else if (i < n_it + n_cv + n_w1) {
        int j = i - n_it - n_cv;
        int n = j / (2 * DIM), k = j % (2 * DIM);
        T1[j] = __float2half_rn(W1[(size_t)k * HID + n]);
    } else {
        int j = i - n_it - n_cv - n_w1;
        if (j >= n_w2) return;
        int n = j / HID, k = j % HID;
        T2[j] = __float2half_rn(W2[(size_t)k * HID + n]);
    }
}

// ---------------- chunked scans ----------------
// Pass 1: serial scan, stores only chunk-boundary states (tiny writes).
// g_bnd layout: [b][chunk][slot][DIM]; slots 0-2 = fwd l1,l2,lc; 3-4 = bwd r1,r2
__global__ void scan_bounds_kernel(const float* __restrict__ yes_t,
                                   const float* __restrict__ no_t) {
    int idx = blockIdx.x * blockDim.x + threadIdx.x;
    if (idx >= 2 * NB * 64) return;
    int half = idx / (NB * 64);
    int r = idx % (NB * 64);
    int b = r >> 6, f0 = (r & 63) << 2;
    float4 yf = *(const float4*)(yes_t + f0);
    float4 nf = *(const float4*)(no_t + f0);
    if (half == 0) {
        float4 l1 = {0,0,0,0}, l2 = {0,0,0,0}, lc = {0,0,0,0};
        for (int i = 0; i < S2; i++) {
            int tok = b * S2 + i;
            if (i % CS == 0) {
                float* dst = g_bnd + ((size_t)(b * NCH + i / CS) * 5) * DIM + f0;
                *(float4*)dst = l1;
                *(float4*)(dst + DIM) = l2;
                *(float4*)(dst + 2 * DIM) = lc;
            }
            float a = g_active[tok], m = g_mask[tok], lt = g_ltp[tok];
            float w = a * m * m, c = 1.f - a * m + EPSF;
            float4 sv = *(const float4*)(g_seq + (size_t)tok * DIM + f0);
            float4 base;
            base.x = sv.x + lt * yf.x + (1.f - lt) * nf.x;
            base.y = sv.y + lt * yf.y + (1.f - lt) * nf.y;
            base.z = sv.z + lt * yf.z + (1.f - lt) * nf.z;
            base.w = sv.w + lt * yf.w + (1.f - lt) * nf.w;
            float4 nl2;
            nl2.x = w * l1.x + c * l2.x; nl2.y = w * l1.y + c * l2.y;
            nl2.z = w * l1.z + c * l2.z; nl2.w = w * l1.w + c * l2.w;
            l1.x = w * base.x + c * l1.x; l1.y = w * base.y + c * l1.y;
            l1.z = w * base.z + c * l1.z; l1.w = w * base.w + c * l1.w;
            lc.x = w * sv.x + c * lc.x; lc.y = w * sv.y + c * lc.y;
            lc.z = w * sv.z + c * lc.z; lc.w = w * sv.w + c * lc.w;
            l2 = nl2;
        }
    } else {
        float4 r1 = {0,0,0,0}, r2 = {0,0,0,0};
        for (int i = S2 - 1; i >= 0; i--) {
            int tok = b * S2 + i;
            if (i == S2 - 1 || (i % CS) == CS - 1) {
                float* dst = g_bnd + ((size_t)(b * NCH + i / CS) * 5 + 3) * DIM + f0;
                *(float4*)dst = r1;
                *(float4*)(dst + DIM) = r2;
            }
            float a = g_active[tok], m = g_mask[tok], lt = g_ltp[tok];
            float w = a * m * m, c = 1.f - a * m + EPSF;
            float4 sv = *(const float4*)(g_seq + (size_t)tok * DIM + f0);
            float4 base;
            base.x = sv.x + lt * yf.x + (1.f - lt) * nf.x;
            base.y = sv.y + lt * yf.y + (1.f - lt) * nf.y;
            base.z = sv.z + lt * yf.z + (1.f - lt) * nf.z;
            base.w = sv.w + lt * yf.w + (1.f - lt) * nf.w;
            float4 nr2;
            nr2.x = w * r1.x + c * r2.x; nr2.y = w * r1.y + c * r2.y;
            nr2.z = w * r1.z + c * r2.z; nr2.w = w * r1.w + c * r2.w;
            r1.x = w * base.x + c * r1.x; r1.y = w * base.y + c * r1.y;
            r1.z = w * base.z + c * r1.z; r1.w = w * base.w + c * r1.w;
            r2 = nr2;
        }
    }
}

// Pass 2: per-chunk materialization from boundary states (8x the warps for stores)
__global__ void scan_mat_kernel(const float* __restrict__ yes_t,
                                const float* __restrict__ no_t) {
    int idx = blockIdx.x * blockDim.x + threadIdx.x;
    if (idx >= 2 * NB * NCH * 64) return;
    int half = idx / (NB * NCH * 64);
    int r = idx % (NB * NCH * 64);
    int b = r / (NCH * 64);
    int c = (r >> 6) % NCH;
    int f0 = (r & 63) << 2;
    int i0 = c * CS, i1 = min(i0 + CS, S2);
    float4 yf = *(const float4*)(yes_t + f0);
    float4 nf = *(const float4*)(no_t + f0);
    const float* bnd = g_bnd + ((size_t)(b * NCH + c) * 5) * DIM + f0;
    if (half == 0) {
        float4 l1 = *(const float4*)bnd;
        float4 l2 = *(const float4*)(bnd + DIM);
        float4 lc = *(const float4*)(bnd + 2 * DIM);
        for (int i = i0; i < i1; i++) {
            int tok = b * S2 + i;
            float a = g_active[tok], m = g_mask[tok], lt = g_ltp[tok];
            float w = a * m * m, cc = 1.f - a * m + EPSF;
            float4 sv = *(const float4*)(g_seq + (size_t)tok * DIM + f0);
            float4 base;
            base.x = sv.x + lt * yf.x + (1.f - lt) * nf.x;
            base.y = sv.y + lt * yf.y + (1.f - lt) * nf.y;
            base.z = sv.z + lt * yf.z + (1.f - lt) * nf.z;
            base.w = sv.w + lt * yf.w + (1.f - lt) * nf.w;
            size_t fl = (size_t)tok * WD;
            st4h(g_flat + fl + 0 * DIM + f0, l2);
            st4h(g_flat + fl + 1 * DIM + f0, l1);
            size_t cp = (size_t)tok * 2 * DIM;
            st4h(g_cc + cp + f0,       lc);
            st4h(g_cc + cp + DIM + f0, sv);
            float4 nl2;
            nl2.x = w * l1.x + cc * l2.x; nl2.y = w * l1.y + cc * l2.y;
            nl2.z = w * l1.z + cc * l2.z; nl2.w = w * l1.w + cc * l2.w;
            l1.x = w * base.x + cc * l1.x; l1.y = w * base.y + cc * l1.y;
            l1.z = w * base.z + cc * l1.z; l1.w = w * base.w + cc * l1.w;
            lc.x = w * sv.x + cc * lc.x; lc.y = w * sv.y + cc * lc.y;
            lc.z = w * sv.z + cc * lc.z; lc.w = w * sv.w + cc * lc.w;
            l2 = nl2;
        }
    } else {
        float4 r1 = *(const float4*)(bnd + 3 * DIM);
        float4 r2 = *(const float4*)(bnd + 4 * DIM);
        for (int i = i1 - 1; i >= i0; i--) {
            int tok = b * S2 + i;
            float a = g_active[tok], m = g_mask[tok], lt = g_ltp[tok];
            float w = a * m * m, cc = 1.f - a * m + EPSF;
            float4 sv = *(const float4*)(g_seq + (size_t)tok * DIM + f0);
            float4 base;
            base.x = sv.x + lt * yf.x + (1.f - lt) * nf.x;
            base.y = sv.y + lt * yf.y + (1.f - lt) * nf.y;
            base.z = sv.z + lt * yf.z + (1.f - lt) * nf.z;
            base.w = sv.w + lt * yf.w + (1.f - lt) * nf.w;
            size_t fl = (size_t)tok * WD;
            st4h(g_flat + fl + 2 * DIM + f0, base);
            st4h(g_flat + fl + 3 * DIM + f0, r1);
            st4h(g_flat + fl + 4 * DIM + f0, r2);
            float4 nr2;
            nr2.x = w * r1.x + cc * r2.x; nr2.y = w * r1.y + cc * r2.y;
            nr2.z = w * r1.z + cc * r2.z; nr2.w = w * r1.w + cc * r2.w;
            r1.x = w * base.x + cc * r1.x; r1.y = w * base.y + cc * r1.y;
            r1.z = w * base.z + cc * r1.z; r1.w = w * base.w + cc * r1.w;
            r2 = nr2;
        }
    }
}

// ---------------- per-step kernels ----------------
__global__ void combine_kernel(const float* __restrict__ lng, const float* __restrict__ lnb) {
    int tok = blockIdx.x, f = threadIdx.x;
    const float* ct = g_contents + (size_t)tok * HID;
    size_t cp = (size_t)tok * 2 * DIM;
    float lc = __half2float(g_cc[cp + f]);
    float sv = g_seq[(size_t)tok * DIM + f];
    float g0 = 1.f / (1.f + expf(-ct[0 * DIM + f]));
    float g1 = 1.f / (1.f + expf(-ct[1 * DIM + f]));
    float g2 = 1.f / (1.f + expf(-ct[2 * DIM + f]));
    float y = g0 * lc + g1 * sv + g2 * ct[3 * DIM + f];
    float mean = blockReduceSum256(y) * (1.f / DIM);
    float d = y - mean;
    float r = rsqrtf(blockReduceSum256(d * d) * (1.f / DIM) + 1e-5f);
    float comp = d * r * lng[f] + lnb[f];
    float mx = g_mx;
    float et = expf(g_tsc[tok] - mx) * g_selp[tok];
    float tp = et / (et + expf(-mx) + EPSF);
    if (f == 0) g_tp[tok] = tp;
    g_seq[(size_t)tok * DIM + f] = (tp * comp + (1.f - tp) * sv) * g_mask[tok];
}

__global__ void deact_kernel() {
    __shared__ float s_a[S2], s_m[S2], s_tp[S2];
    int b = blockIdx.x;
    if (b == 0 && threadIdx.x == 0) g_mx = 0.f;
    for (int i = threadIdx.x; i < S2; i += blockDim.x) {
        int tok = b * S2 + i;
        s_a[i] = g_active[tok]; s_m[i] = g_mask[tok]; s_tp[i] = g_tp[tok];
    }
    __syncthreads();
    if (threadIdx.x == 0) {
        float dacc = 0.f;
        for (int j = S2 - 1; j >= 0; j--) {
            float a = s_a[j], m = s_m[j], tp = s_tp[j];
            float de = a * m * m * dacc;
            s_a[j] = fminf(fmaxf(a * (1.f - de), 0.f), 1.f) * m;
            dacc = tp + (1.f - a * m + EPSF) * dacc;
        }
    }
    __syncthreads();
    for (int i = threadIdx.x; i < S2; i += blockDim.x) {
        int tok = b * S2 + i;
        g_active[tok] = s_a[i];
        g_ltp[tok]    = s_tp[i];
    }
}

__global__ void copy_out_kernel(float* __restrict__ out) {
    int idx = blockIdx.x * blockDim.x + threadIdx.x;
    if (idx < NTOK * DIM) out[idx] = g_seq[idx];
}

// ---------------- launch ----------------
extern "C" void kernel_launch(void* const* d_in, const int* in_sizes, int n_in,
                              void* d_out, int out_size) {
    const float* sequence   = (const float*)d_in[0];
    const float* input_mask = (const float*)d_in[1];
    const float* START = (const float*)d_in[2];
    const float* END   = (const float*)d_in[3];
    const float* yes_t = (const float*)d_in[4];
    const float* no_t  = (const float*)d_in[5];
    const float* convW = (const float*)d_in[6];
    const float* convb = (const float*)d_in[7];
    const float* scW   = (const float*)d_in[8];
    const float* scb   = (const float*)d_in[9];
    const float* itW   = (const float*)d_in[10];
    const float* itb   = (const float*)d_in[11];
    const float* w1W   = (const float*)d_in[12];
    const float* w1b   = (const float*)d_in[13];
    const float* w2W   = (const float*)d_in[14];
    const float* w2b   = (const float*)d_in[15];
    const float* lng   = (const float*)d_in[16];
    const float* lnb   = (const float*)d_in[17];
    float* out = (float*)d_out;

    __half *p_flat, *p_cc, *p_inter, *p_convWt, *p_w1Wt, *p_w2Wt, *p_itWt;
    float *p_contents, *p_convOut;
    cudaGetSymbolAddress((void**)&p_flat, g_flat);
    cudaGetSymbolAddress((void**)&p_cc, g_cc);
    cudaGetSymbolAddress((void**)&p_inter, g_inter);
    cudaGetSymbolAddress((void**)&p_contents, g_contents);
    cudaGetSymbolAddress((void**)&p_convOut, g_convOut);
    cudaGetSymbolAddress((void**)&p_convWt, g_convWt);
    cudaGetSymbolAddress((void**)&p_w1Wt, g_w1Wt);
    cudaGetSymbolAddress((void**)&p_w2Wt, g_w2Wt);
    cudaGetSymbolAddress((void**)&p_itWt, g_itWt);

    const int SMEMB = 2 * STG_BYTES;   // 110592
    cudaFuncSetAttribute(mma_gemm<0,0,0>, cudaFuncAttributeMaxDynamicSharedMemorySize, SMEMB);
    cudaFuncSetAttribute(mma_gemm<1,1,0>, cudaFuncAttributeMaxDynamicSharedMemorySize, SMEMB);
    cudaFuncSetAttribute(mma_gemm<1,0,1>, cudaFuncAttributeMaxDynamicSharedMemorySize, SMEMB);

    const int THR = 256;
    const int GM = (NTOK + 127) / 128;   // 129
    const int PACK_N = DIM * DIM + DIM * WD + HID * 2 * DIM + HID * HID;

    init_masks_kernel<<<(NTOK + THR - 1) / THR, THR>>>(input_mask);
    init_seqpre_kernel<<<(NTOK * DIM + THR - 1) / THR, THR>>>(sequence, START, END);
    pack_all<<<(PACK_N + THR - 1) / THR, THR>>>(itW, p_itWt, convW, p_convWt,
                                                w1W, p_w1Wt, w2W, p_w2Wt);

    mma_gemm<0,0,0><<<dim3(1, GM), 512, SMEMB>>>(p_cc, 2 * DIM,
        p_itWt, itb, p_convOut, DIM, NTOK, DIM, nullptr, nullptr);
    ln_init_kernel<<<NTOK, DIM>>>(lng, lnb);

    for (int s = 0; s < NSTEPS; s++) {
        scan_bounds_kernel<<<(2 * NB * 64 + THR - 1) / THR, THR>>>(yes_t, no_t);
        scan_mat_kernel<<<(2 * NB * NCH * 64 + THR - 1) / THR, THR>>>(yes_t, no_t);
        mma_gemm<1,0,1><<<dim3(1, GM), 512, SMEMB>>>(p_flat, WD,
            p_convWt, convb, nullptr, DIM, NTOK, WD, scW, scb);
        mma_gemm<1,1,0><<<dim3(4, GM), 512, SMEMB>>>(p_cc, 2 * DIM,
            p_w1Wt, w1b, p_inter, HID, NTOK, 2 * DIM, nullptr, nullptr);
        mma_gemm<0,0,0><<<dim3(4, GM), 512, SMEMB>>>(p_inter, HID,
            p_w2Wt, w2b, p_contents, HID, NTOK, HID, nullptr, nullptr);
        combine_kernel<<<NTOK, DIM>>>(lng, lnb);
        deact_kernel<<<NB, 128>>>();
    }

    copy_out_kernel<<<(NTOK * DIM + THR - 1) / THR, THR>>>(out);
}

// round 13
// speedup vs baseline: 1.2333x; 1.0655x over previous
#include <cuda_runtime.h>
#include <cuda_fp16.h>
#include <math.h>
#include <stdint.h>

#define NB   32
#define SEQL 512
#define DIM  256
#define S2   514
#define NTOK (NB * S2)
#define HID  1024
#define WD   1280
#define NSTEPS 6
#define EPSF 1e-9f

static __device__ __align__(256) __half g_flat[NTOK * WD];
static __device__ __align__(256) __half g_cc[NTOK * 2 * DIM];
static __device__ __align__(256) __half g_inter[NTOK * HID];
static __device__ __align__(256) float g_contents[NTOK * HID];
static __device__ __align__(256) float g_convOut[NTOK * DIM];
static __device__ __align__(256) float g_seq[NTOK * DIM];
static __device__ float g_tsc[NTOK], g_ltp[NTOK];
static __device__ float g_active[NTOK], g_mask[NTOK], g_selp[NTOK], g_endm[NTOK];
static __device__ float g_mxbuf[2];
static __device__ __align__(256) __half g_convWt[DIM * WD];
static __device__ __align__(256) __half g_w1Wt[HID * 2 * DIM];
static __device__ __align__(256) __half g_w2Wt[HID * HID];
static __device__ __align__(256) __half g_itWt[DIM * DIM];

__device__ __forceinline__ float geluf(float x) {
    float x3 = x * x * x;
    return 0.5f * x * (1.f + tanhf(0.7978845608028654f * (x + 0.044715f * x3)));
}
__device__ __forceinline__ void st4h(__half* H, float4 v) {
    ushort4 h;
    h.x = __half_as_ushort(__float2half_rn(v.x));
    h.y = __half_as_ushort(__float2half_rn(v.y));
    h.z = __half_as_ushort(__float2half_rn(v.z));
    h.w = __half_as_ushort(__float2half_rn(v.w));
    *(ushort4*)H = h;
}
__device__ __forceinline__ float blockReduceSum256(float v) {
    __shared__ float sh[33];
    int lane = threadIdx.x & 31, wid = threadIdx.x >> 5;
#pragma unroll
    for (int o = 16; o; o >>= 1) v += __shfl_down_sync(0xffffffffu, v, o);
    __syncthreads();
    if (lane == 0) sh[wid] = v;
    __syncthreads();
    if (wid == 0) {
        float t = (lane < 8) ? sh[lane] : 0.f;
#pragma unroll
        for (int o = 16; o; o >>= 1) t += __shfl_down_sync(0xffffffffu, t, o);
        if (lane == 0) sh[32] = t;
    }
    __syncthreads();
    return sh[32];
}

// ---------------- mma.sync helpers ----------------
__device__ __forceinline__ uint32_t s2u(const void* p) { return (uint32_t)__cvta_generic_to_shared(p); }
__device__ __forceinline__ void ldm4(uint32_t* r, uint32_t a) {
    asm volatile("ldmatrix.sync.aligned.m8n8.x4.shared.b16 {%0,%1,%2,%3}, [%4];"
                 : "=r"(r[0]), "=r"(r[1]), "=r"(r[2]), "=r"(r[3]) : "r"(a));
}
__device__ __forceinline__ void mma16816(float* c, const uint32_t* a, const uint32_t* b) {
    asm volatile("mma.sync.aligned.m16n8k16.row.col.f32.f16.f16.f32 "
                 "{%0,%1,%2,%3},{%4,%5,%6,%7},{%8,%9},{%0,%1,%2,%3};"
                 : "+f"(c[0]), "+f"(c[1]), "+f"(c[2]), "+f"(c[3])
                 : "r"(a[0]), "r"(a[1]), "r"(a[2]), "r"(a[3]), "r"(b[0]), "r"(b[1]));
}
__device__ __forceinline__ void cpasync16(uint32_t dst, const void* src, int srcsize) {
    asm volatile("cp.async.cg.shared.global [%0], [%1], 16, %2;"
                 :: "r"(dst), "l"(src), "r"(srcsize) : "memory");
}

// ---------------- shared GEMM mainloop (3-stage cp.async pipeline) ----------------
#define STG_BYTES 55296
#define ROWB 144
#define SMEMB (3 * STG_BYTES)   // 165888
__device__ __forceinline__ void gemm_main(
    float acc[4][4][4], const __half* __restrict__ A, int lda,
    const __half* __restrict__ B, int M, int K, int bm, int bn,
    uint32_t sbase, int tid, int m0, int n0w, int lane)
{
#pragma unroll
    for (int i = 0; i < 4; i++)
#pragma unroll
        for (int j = 0; j < 4; j++)
#pragma unroll
            for (int e = 0; e < 4; e++) acc[i][j][e] = 0.f;

    const int NK = K >> 6;
    auto fill = [&](int st, int kt) {
        int k0 = kt << 6;
#pragma unroll
        for (int q = 0; q < 6; q++) {
            int u = tid + q * 512;
            const __half* src;
            uint32_t dst;
            int sz = 16;
            if (u < 1024) {
                int r = u >> 3, c = u & 7;
                int gr = bm + r;
                if (gr >= M) { gr = 0; sz = 0; }
                src = A + (size_t)gr * lda + k0 + c * 8;
                dst = sbase + st * STG_BYTES + r * ROWB + c * 16;
            } else {
                int v = u - 1024;
                int r = (v >> 3) & 255, c = v & 7;
                src = B + (size_t)(bn + r) * K + k0 + c * 8;
                dst = sbase + st * STG_BYTES + 18432 + r * ROWB + c * 16;
            }
            cpasync16(dst, src, sz);
        }
        asm volatile("cp.async.commit_group;" ::: "memory");
    };

    fill(0, 0);
    fill(1, 1);             // NK >= 4 for all our GEMMs
    for (int kt = 0; kt < NK; kt++) {
        if (kt + 2 < NK) {
            fill((kt + 2) % 3, kt + 2);
            asm volatile("cp.async.wait_group 2;" ::: "memory");
        } else if (kt + 1 < NK) {
            asm volatile("cp.async.wait_group 1;" ::: "memory");
        } else {
            asm volatile("cp.async.wait_group 0;" ::: "memory");
        }
        __syncthreads();

        const uint32_t sA = sbase + (kt % 3) * STG_BYTES;
        const uint32_t sB = sA + 18432;
#pragma unroll
        for (int kh = 0; kh < 4; kh++) {
            uint32_t a[4][4], bfr[2][4];
            int aoff = (m0 + (lane & 15)) * ROWB + kh * 32 + (lane >> 4) * 16;
            int boff = (n0w + ((lane & 7) | ((lane >> 1) & 8))) * ROWB
                       + kh * 32 + ((lane >> 3) & 1) * 16;
#pragma unroll
            for (int nt = 0; nt < 2; nt++)
                ldm4(bfr[nt], sB + boff + nt * 16 * ROWB);
#pragma unroll
            for (int mi = 0; mi < 4; mi++) ldm4(a[mi], sA + aoff + mi * 16 * ROWB);
#pragma unroll
            for (int mi = 0; mi < 4; mi++)
#pragma unroll
                for (int fi = 0; fi < 4; fi++)
                    mma16816(acc[mi][fi], a[mi], &bfr[fi >> 1][(fi & 1) * 2]);
        }
        __syncthreads();
    }
}

// plain GEMM -> fp32 C (+bias), used for itW and w2
__global__ __launch_bounds__(512, 1) void mma_gemm_f(
    const __half* __restrict__ A, int lda, const __half* __restrict__ B,
    const float* __restrict__ bias, float* __restrict__ C, int ldc, int M, int K)
{
    extern __shared__ char smem[];
    const uint32_t sbase = s2u(smem);
    const int tid = threadIdx.x, w = tid >> 5, lane = tid & 31;
    const int bm = blockIdx.y * 128, bn = blockIdx.x * 256;
    const int m0 = (w & 1) * 64, n0w = (w >> 1) * 32;
    float acc[4][4][4];
    gemm_main(acc, A, lda, B, M, K, bm, bn, sbase, tid, m0, n0w, lane);
    int tq = lane >> 2, tr = lane & 3;
#pragma unroll
    for (int mi = 0; mi < 4; mi++)
#pragma unroll
        for (int fi = 0; fi < 4; fi++) {
            int col = bn + n0w + fi * 8 + tr * 2;
            float b0 = bias[col], b1 = bias[col + 1];
#pragma unroll
            for (int half = 0; half < 2; half++) {
                int row = bm + m0 + mi * 16 + tq + half * 8;
                if (row >= M) continue;
                *(float2*)(C + (size_t)row * ldc + col) =
                    make_float2(acc[mi][fi][half * 2 + 0] + b0,
                                acc[mi][fi][half * 2 + 1] + b1);
            }
        }
}

// fused conv/score + w1 GEMM: blockIdx.x in [0,3] = w1 tiles, ==4 = conv+score
__global__ __launch_bounds__(512, 1) void mma_gemm_fused(
    const float* __restrict__ convb, const float* __restrict__ scW,
    const float* __restrict__ scb,   const float* __restrict__ w1b,
    int mxslot)
{
    extern __shared__ char smem[];
    const uint32_t sbase = s2u(smem);
    const int tid = threadIdx.x, w = tid >> 5, lane = tid & 31;
    const int bm = blockIdx.y * 128;
    const int m0 = (w & 1) * 64, n0w = (w >> 1) * 32;
    const bool isConv = (blockIdx.x == 4);
    const int bn = isConv ? 0 : blockIdx.x * 256;
    const __half* A  = isConv ? g_flat : g_cc;
    const __half* B  = isConv ? g_convWt : g_w1Wt;
    const int lda = isConv ? WD : 2 * DIM;
    const int K   = isConv ? WD : 2 * DIM;

    float acc[4][4][4];
    gemm_main(acc, A, lda, B, NTOK, K, bm, bn, sbase, tid, m0, n0w, lane);

    int tq = lane >> 2, tr = lane & 3;
    if (isConv) {
        float* srow = (float*)smem;
        if (tid < 128) srow[tid] = 0.f;
        __syncthreads();
#pragma unroll
        for (int mi = 0; mi < 4; mi++)
#pragma unroll
            for (int half = 0; half < 2; half++) {
                int rl = m0 + mi * 16 + tq + half * 8;
                float s = 0.f;
#pragma unroll
                for (int fi = 0; fi < 4; fi++) {
                    int col = bn + n0w + fi * 8 + tr * 2;
                    float v0 = geluf(acc[mi][fi][half * 2 + 0] + convb[col]);
                    float v1 = geluf(acc[mi][fi][half * 2 + 1] + convb[col + 1]);
                    s += v0 * scW[col] + v1 * scW[col + 1];
                }
                atomicAdd(&srow[rl], s);
            }
        __syncthreads();
        if (tid < 128) {
            int gr = bm + tid;
            if (gr < NTOK) {
                float t = srow[tid] + scb[0];
                g_tsc[gr] = t;
                atomicMax((unsigned int*)&g_mxbuf[mxslot],
                          __float_as_uint(fmaxf(t, 0.f)));
            }
        }
    } else {
#pragma unroll
        for (int mi = 0; mi < 4; mi++)
#pragma unroll
            for (int fi = 0; fi < 4; fi++) {
                int col = bn + n0w + fi * 8 + tr * 2;
                float b0 = w1b[col], b1 = w1b[col + 1];
#pragma unroll
                for (int half = 0; half < 2; half++) {
                    int row = bm + m0 + mi * 16 + tq + half * 8;
                    if (row >= NTOK) continue;
                    float v0 = geluf(acc[mi][fi][half * 2 + 0] + b0);
                    float v1 = geluf(acc[mi][fi][half * 2 + 1] + b1);
                    ushort2 h;
                    h.x = __half_as_ushort(__float2half_rn(v0));
                    h.y = __half_as_ushort(__float2half_rn(v1));
                    *(ushort2*)(g_inter + (size_t)row * HID + col) = h;
                }
            }
    }
}

// ---------------- init kernels ----------------
__global__ void init_masks_kernel(const float* __restrict__ im) {
    int idx = blockIdx.x * blockDim.x + threadIdx.x;
    if (idx < 2) g_mxbuf[idx] = 0.f;
    if (idx >= NTOK) return;
    int b = idx / S2, i = idx % S2;
    auto mask_yes = [&](int j) -> float { return (j <= 1) ? 1.f : im[b * SEQL + (j - 2)]; };
    auto mask_no_end = [&](int j) -> float {
        if (j == 0) return 1.f;
        if (j <= SEQL) return im[b * SEQL + (j - 1)];
        return 0.f;
    };
    float my = mask_yes(i), mne = mask_no_end(i);
    float mask_no_start = (i == 0) ? 0.f : my;
    float last_token = (i < S2 - 1) ? (mask_yes(i + 1) - mask_no_end(i + 1)) : 0.f;
    g_mask[idx] = my;
    g_endm[idx] = my - mne;
    g_selp[idx] = mask_no_start * mne * (1.f - last_token);
    g_active[idx] = my;
    g_ltp[idx] = 0.f;
}

__global__ void init_seqpre_kernel(const float* __restrict__ seqin,
                                   const float* __restrict__ START,
                                   const float* __restrict__ END) {
    int idx = blockIdx.x * blockDim.x + threadIdx.x;
    if (idx >= NTOK * DIM) return;
    int tok = idx / DIM, f = idx % DIM;
    int b = tok / S2, i = tok % S2;
    float base;
    if (i == 0)          base = START[f];
    else if (i <= SEQL)  base = seqin[((size_t)b * SEQL + (i - 1)) * DIM + f];
    else                 base = 0.f;
    float e = g_endm[tok];
    float x = e * END[f] + (1.f - e) * base;
    g_cc[(size_t)tok * (2 * DIM) + f] = __float2half_rn(x);
}

__global__ void ln_init_kernel(const float* __restrict__ lng, const float* __restrict__ lnb) {
    int tok = blockIdx.x, f = threadIdx.x;
    float x = g_convOut[(size_t)tok * DIM + f];
    float mean = blockReduceSum256(x) * (1.f / DIM);
    float d = x - mean;
    float r = rsqrtf(blockReduceSum256(d * d) * (1.f / DIM) + 1e-5f);
    g_seq[(size_t)tok * DIM + f] = (d * r * lng[f] + lnb[f]) * g_mask[tok];
}

__global__ void pack_all(const float* __restrict__ Wit, __half* __restrict__ Tit,
                         const float* __restrict__ Wcv, __half* __restrict__ Tcv,
                         const float* __restrict__ W1,  __half* __restrict__ T1,
                         const float* __restrict__ W2,  __half* __restrict__ T2) {
    int i = blockIdx.x * blockDim.x + threadIdx.x;
    const int n_it = DIM * DIM;
    const int n_cv = DIM * WD;
    const int n_w1 = HID * 2 * DIM;
    const int n_w2 = HID * HID;
    if (i < n_it) {
        int n = i / DIM, k = i % DIM;
        Tit[i] = __float2half_rn(Wit[(size_t)k * DIM + n]);
    } else if (i < n_it + n_cv) {
        int j = i - n_it;
        int n = j / WD, k = j % WD;
        Tcv[j] = __float2half_rn(Wcv[(size_t)k * DIM + n]);
    } else if (i < n_it + n_cv + n_w1) {
        int j = i - n_it - n_cv;
        int n = j / (2 * DIM), k = j % (2 * DIM);
        T1[j] = __float2half_rn(W1[(size_t)k * HID + n]);
    } else {
        int j = i - n_it - n_cv - n_w1;
        if (j >= n_w2) return;
        int n = j / HID, k = j % HID;
        T2[j] = __float2half_rn(W2[(size_t)k * HID + n]);
    }
}

// ---------------- merged scan kernel (R10 form) ----------------
__global__ void scan_kernel(const float* __restrict__ yes_t, const float* __restrict__ no_t) {
    int idx = blockIdx.x * blockDim.x + threadIdx.x;
    if (idx < NB * 64) {
        int b = idx >> 6, f0 = (idx & 63) << 2;
        float4 yf = *(const float4*)(yes_t + f0);
        float4 nf = *(const float4*)(no_t + f0);
        float4 l1 = {0,0,0,0}, l2 = {0,0,0,0}, lc = {0,0,0,0};
        for (int i = 0; i < S2; i++) {
            int tok = b * S2 + i;
            float a = g_active[tok], m = g_mask[tok], lt = g_ltp[tok];
            float w = a * m * m, c = 1.f - a * m + EPSF;
            float4 sv = *(const float4*)(g_seq + (size_t)tok * DIM + f0);
            float4 base;
            base.x = sv.x + lt * yf.x + (1.f - lt) * nf.x;
            base.y = sv.y + lt * yf.y + (1.f - lt) * nf.y;
            base.z = sv.z + lt * yf.z + (1.f - lt) * nf.z;
            base.w = sv.w + lt * yf.w + (1.f - lt) * nf.w;
            size_t fl = (size_t)tok * WD;
            st4h(g_flat + fl + 0 * DIM + f0, l2);
            st4h(g_flat + fl + 1 * DIM + f0, l1);
            size_t cp = (size_t)tok * 2 * DIM;
            st4h(g_cc + cp + f0,       lc);
            st4h(g_cc + cp + DIM + f0, sv);
            float4 nl2;
            nl2.x = w * l1.x + c * l2.x; nl2.y = w * l1.y + c * l2.y;
            nl2.z = w * l1.z + c * l2.z; nl2.w = w * l1.w + c * l2.w;
            l1.x = w * base.x + c * l1.x; l1.y = w * base.y + c * l1.y;
            l1.z = w * base.z + c * l1.z; l1.w = w * base.w + c * l1.w;
            lc.x = w * sv.x + c * lc.x; lc.y = w * sv.y + c * lc.y;
            lc.z = w * sv.z + c * lc.z; lc.w = w * sv.w + c * lc.w;
            l2 = nl2;
        }
    } else {
        int j = idx - NB * 64;
        if (j >= NB * 64) return;
        int b = j >> 6, f0 = (j & 63) << 2;
        float4 yf = *(const float4*)(yes_t + f0);
        float4 nf = *(const float4*)(no_t + f0);
        float4 r1 = {0,0,0,0}, r2 = {0,0,0,0};
        for (int i = S2 - 1; i >= 0; i--) {
            int tok = b * S2 + i;
            float a = g_active[tok], m = g_mask[tok], lt = g_ltp[tok];
            float w = a * m * m, c = 1.f - a * m + EPSF;
            float4 sv = *(const float4*)(g_seq + (size_t)tok * DIM + f0);
            float4 base;
            base.x = sv.x + lt * yf.x + (1.f - lt) * nf.x;
            base.y = sv.y + lt * yf.y + (1.f - lt) * nf.y;
            base.z = sv.z + lt * yf.z + (1.f - lt) * nf.z;
            base.w = sv.w + lt * yf.w + (1.f - lt) * nf.w;
            size_t fl = (size_t)tok * WD;
            st4h(g_flat + fl + 2 * DIM + f0, base);
            st4h(g_flat + fl + 3 * DIM + f0, r1);
            st4h(g_flat + fl + 4 * DIM + f0, r2);
            float4 nr2;
            nr2.x = w * r1.x + c * r2.x; nr2.y = w * r1.y + c * r2.y;
            nr2.z = w * r1.z + c * r2.z; nr2.w = w * r1.w + c * r2.w;
            r1.x = w * base.x + c * r1.x; r1.y = w * base.y + c * r1.y;
            r1.z = w * base.z + c * r1.z; r1.w = w * base.w + c * r1.w;
            r2 = nr2;
        }
    }
}

// ---------------- merged combine + deact kernel ----------------
// blocks [0, NTOK): combine (per token); blocks [NTOK, NTOK+NB): deact (per batch)
__global__ void combine_deact_kernel(const float* __restrict__ lng,
                                     const float* __restrict__ lnb,
                                     int mxslot, float* __restrict__ out) {
    if (blockIdx.x < NTOK) {
        int tok = blockIdx.x, f = threadIdx.x;
        const float* ct = g_contents + (size_t)tok * HID;
        size_t cp = (size_t)tok * 2 * DIM;
        float lc = __half2float(g_cc[cp + f]);
        float sv = g_seq[(size_t)tok * DIM + f];
        float g0 = 1.f / (1.f + expf(-ct[0 * DIM + f]));
        float g1 = 1.f / (1.f + expf(-ct[1 * DIM + f]));
        float g2 = 1.f / (1.f + expf(-ct[2 * DIM + f]));
        float y = g0 * lc + g1 * sv + g2 * ct[3 * DIM + f];
        float mean = blockReduceSum256(y) * (1.f / DIM);
        float d = y - mean;
        float r = rsqrtf(blockReduceSum256(d * d) * (1.f / DIM) + 1e-5f);
        float comp = d * r * lng[f] + lnb[f];
        float mx = g_mxbuf[mxslot];
        float et = expf(g_tsc[tok] - mx) * g_selp[tok];
        float tp = et / (et + expf(-mx) + EPSF);
        float res = (tp * comp + (1.f - tp) * sv) * g_mask[tok];
        g_seq[(size_t)tok * DIM + f] = res;
        if (out) out[(size_t)tok * DIM + f] = res;
    } else {
        __shared__ float s_a[S2], s_m[S2], s_tp[S2];
        int b = blockIdx.x - NTOK;
        float mx = g_mxbuf[mxslot];
        if (b == 0 && threadIdx.x == 0) g_mxbuf[mxslot ^ 1] = 0.f; // zero NEXT slot
        float en = expf(-mx);
        for (int i = threadIdx.x; i < S2; i += blockDim.x) {
            int tok = b * S2 + i;
            s_a[i] = g_active[tok]; s_m[i] = g_mask[tok];
            float et = expf(g_tsc[tok] - mx) * g_selp[tok];
            s_tp[i] = et / (et + en + EPSF);
        }
        __syncthreads();
        if (threadIdx.x == 0) {
            float dacc = 0.f;
            for (int j = S2 - 1; j >= 0; j--) {
                float a = s_a[j], m = s_m[j], tp = s_tp[j];
                float de = a * m * m * dacc;
                s_a[j] = fminf(fmaxf(a * (1.f - de), 0.f), 1.f) * m;
                dacc = tp + (1.f - a * m + EPSF) * dacc;
            }
        }
        __syncthreads();
        for (int i = threadIdx.x; i < S2; i += blockDim.x) {
            int tok = b * S2 + i;
            g_active[tok] = s_a[i];
            g_ltp[tok]    = s_tp[i];
        }
    }
}

// ---------------- launch ----------------
extern "C" void kernel_launch(void* const* d_in, const int* in_sizes, int n_in,
                              void* d_out, int out_size) {
    const float* sequence   = (const float*)d_in[0];
    const float* input_mask = (const float*)d_in[1];
    const float* START = (const float*)d_in[2];
    const float* END   = (const float*)d_in[3];
    const float* yes_t = (const float*)d_in[4];
    const float* no_t  = (const float*)d_in[5];
    const float* convW = (const float*)d_in[6];
    const float* convb = (const float*)d_in[7];
    const float* scW   = (const float*)d_in[8];
    const float* scb   = (const float*)d_in[9];
    const float* itW   = (const float*)d_in[10];
    const float* itb   = (const float*)d_in[11];
    const float* w1W   = (const float*)d_in[12];
    const float* w1b   = (const float*)d_in[13];
    const float* w2W   = (const float*)d_in[14];
    const float* w2b   = (const float*)d_in[15];
    const float* lng   = (const float*)d_in[16];
    const float* lnb   = (const float*)d_in[17];
    float* out = (float*)d_out;

    __half *p_cc, *p_inter, *p_convWt, *p_w1Wt, *p_w2Wt, *p_itWt;
    float *p_contents, *p_convOut;
    cudaGetSymbolAddress((void**)&p_cc, g_cc);
    cudaGetSymbolAddress((void**)&p_inter, g_inter);
    cudaGetSymbolAddress((void**)&p_contents, g_contents);
    cudaGetSymbolAddress((void**)&p_convOut, g_convOut);
    cudaGetSymbolAddress((void**)&p_convWt, g_convWt);
    cudaGetSymbolAddress((void**)&p_w1Wt, g_w1Wt);
    cudaGetSymbolAddress((void**)&p_w2Wt, g_w2Wt);
    cudaGetSymbolAddress((void**)&p_itWt, g_itWt);

    cudaFuncSetAttribute(mma_gemm_f, cudaFuncAttributeMaxDynamicSharedMemorySize, SMEMB);
    cudaFuncSetAttribute(mma_gemm_fused, cudaFuncAttributeMaxDynamicSharedMemorySize, SMEMB);

    const int THR = 256;
    const int GM = (NTOK + 127) / 128;   // 129
    const int PACK_N = DIM * DIM + DIM * WD + HID * 2 * DIM + HID * HID;

    init_masks_kernel<<<(NTOK + THR - 1) / THR, THR>>>(input_mask);
    init_seqpre_kernel<<<(NTOK * DIM + THR - 1) / THR, THR>>>(sequence, START, END);
    pack_all<<<(PACK_N + THR - 1) / THR, THR>>>(itW, p_itWt, convW, p_convWt,
                                                w1W, p_w1Wt, w2W, p_w2Wt);

    mma_gemm_f<<<dim3(1, GM), 512, SMEMB>>>(p_cc, 2 * DIM, p_itWt, itb,
                                            p_convOut, DIM, NTOK, DIM);
    ln_init_kernel<<<NTOK, DIM>>>(lng, lnb);

    for (int s = 0; s < NSTEPS; s++) {
        int slot = s & 1;
        scan_kernel<<<(2 * NB * 64 + THR - 1) / THR, THR>>>(yes_t, no_t);
        // fused: x=0..3 -> w1 N-tiles, x=4 -> conv+score
        mma_gemm_fused<<<dim3(5, GM), 512, SMEMB>>>(convb, scW, scb, w1b, slot);
        mma_gemm_f<<<dim3(4, GM), 512, SMEMB>>>(p_inter, HID, p_w2Wt, w2b,
                                                p_contents, HID, NTOK, HID);
        combine_deact_kernel<<<NTOK + NB, 256>>>(lng, lnb, slot,
                                                 (s == NSTEPS - 1) ? out : nullptr);
    }
}

// round 14
// speedup vs baseline: 1.2979x; 1.0524x over previous
#include <cuda_runtime.h>
#include <cuda_fp16.h>
#include <math.h>
#include <stdint.h>

#define NB   32
#define SEQL 512
#define DIM  256
#define S2   514
#define NTOK (NB * S2)
#define HID  1024
#define WD   1280
#define NSTEPS 6
#define EPSF 1e-9f

static __device__ __align__(256) __half g_flat[NTOK * WD];
static __device__ __align__(256) __half g_cc[NTOK * 2 * DIM];
static __device__ __align__(256) __half g_inter[NTOK * HID];
static __device__ __align__(256) float g_contents[NTOK * HID];
static __device__ __align__(256) float g_convOut[NTOK * DIM];
static __device__ __align__(256) float g_seq[NTOK * DIM];
static __device__ float g_tsc[NTOK], g_ltp[NTOK];
static __device__ float g_active[NTOK], g_mask[NTOK], g_selp[NTOK], g_endm[NTOK];
static __device__ float g_mxbuf[2];
static __device__ __align__(256) __half g_convWt[DIM * WD];
static __device__ __align__(256) __half g_w1Wt[HID * 2 * DIM];
static __device__ __align__(256) __half g_w2Wt[HID * HID];
static __device__ __align__(256) __half g_itWt[DIM * DIM];

__device__ __forceinline__ float geluf(float x) {
    float x3 = x * x * x;
    return 0.5f * x * (1.f + tanhf(0.7978845608028654f * (x + 0.044715f * x3)));
}
__device__ __forceinline__ float blockReduceSum256(float v) {
    __shared__ float sh[33];
    int lane = threadIdx.x & 31, wid = threadIdx.x >> 5;
#pragma unroll
    for (int o = 16; o; o >>= 1) v += __shfl_down_sync(0xffffffffu, v, o);
    __syncthreads();
    if (lane == 0) sh[wid] = v;
    __syncthreads();
    if (wid == 0) {
        float t = (lane < 8) ? sh[lane] : 0.f;
#pragma unroll
        for (int o = 16; o; o >>= 1) t += __shfl_down_sync(0xffffffffu, t, o);
        if (lane == 0) sh[32] = t;
    }
    __syncthreads();
    return sh[32];
}

// ---------------- mma.sync helpers ----------------
__device__ __forceinline__ uint32_t s2u(const void* p) { return (uint32_t)__cvta_generic_to_shared(p); }
__device__ __forceinline__ void ldm4(uint32_t* r, uint32_t a) {
    asm volatile("ldmatrix.sync.aligned.m8n8.x4.shared.b16 {%0,%1,%2,%3}, [%4];"
                 : "=r"(r[0]), "=r"(r[1]), "=r"(r[2]), "=r"(r[3]) : "r"(a));
}
__device__ __forceinline__ void mma16816(float* c, const uint32_t* a, const uint32_t* b) {
    asm volatile("mma.sync.aligned.m16n8k16.row.col.f32.f16.f16.f32 "
                 "{%0,%1,%2,%3},{%4,%5,%6,%7},{%8,%9},{%0,%1,%2,%3};"
                 : "+f"(c[0]), "+f"(c[1]), "+f"(c[2]), "+f"(c[3])
                 : "r"(a[0]), "r"(a[1]), "r"(a[2]), "r"(a[3]), "r"(b[0]), "r"(b[1]));
}
__device__ __forceinline__ void cpasync16(uint32_t dst, const void* src, int srcsize) {
    asm volatile("cp.async.cg.shared.global [%0], [%1], 16, %2;"
                 :: "r"(dst), "l"(src), "r"(srcsize) : "memory");
}

// ---------------- shared GEMM mainloop (3-stage cp.async pipeline) ----------------
#define STG_BYTES 55296
#define ROWB 144
#define SMEMB (3 * STG_BYTES)   // 165888
__device__ __forceinline__ void gemm_main(
    float acc[4][4][4], const __half* __restrict__ A, int lda,
    const __half* __restrict__ B, int M, int K, int bm, int bn,
    uint32_t sbase, int tid, int m0, int n0w, int lane)
{
#pragma unroll
    for (int i = 0; i < 4; i++)
#pragma unroll
        for (int j = 0; j < 4; j++)
#pragma unroll
            for (int e = 0; e < 4; e++) acc[i][j][e] = 0.f;

    const int NK = K >> 6;
    auto fill = [&](int st, int kt) {
        int k0 = kt << 6;
#pragma unroll
        for (int q = 0; q < 6; q++) {
            int u = tid + q * 512;
            const __half* src;
            uint32_t dst;
            int sz = 16;
            if (u < 1024) {
                int r = u >> 3, c = u & 7;
                int gr = bm + r;
                if (gr >= M) { gr = 0; sz = 0; }
                src = A + (size_t)gr * lda + k0 + c * 8;
                dst = sbase + st * STG_BYTES + r * ROWB + c * 16;
            } else {
                int v = u - 1024;
                int r = (v >> 3) & 255, c = v & 7;
                src = B + (size_t)(bn + r) * K + k0 + c * 8;
                dst = sbase + st * STG_BYTES + 18432 + r * ROWB + c * 16;
            }
            cpasync16(dst, src, sz);
        }
        asm volatile("cp.async.commit_group;" ::: "memory");
    };

    fill(0, 0);
    fill(1, 1);
    for (int kt = 0; kt < NK; kt++) {
        if (kt + 2 < NK) {
            fill((kt + 2) % 3, kt + 2);
            asm volatile("cp.async.wait_group 2;" ::: "memory");
        } else if (kt + 1 < NK) {
            asm volatile("cp.async.wait_group 1;" ::: "memory");
        } else {
            asm volatile("cp.async.wait_group 0;" ::: "memory");
        }
        __syncthreads();

        const uint32_t sA = sbase + (kt % 3) * STG_BYTES;
        const uint32_t sB = sA + 18432;
#pragma unroll
        for (int kh = 0; kh < 4; kh++) {
            uint32_t a[4][4], bfr[2][4];
            int aoff = (m0 + (lane & 15)) * ROWB + kh * 32 + (lane >> 4) * 16;
            int boff = (n0w + ((lane & 7) | ((lane >> 1) & 8))) * ROWB
                       + kh * 32 + ((lane >> 3) & 1) * 16;
#pragma unroll
            for (int nt = 0; nt < 2; nt++)
                ldm4(bfr[nt], sB + boff + nt * 16 * ROWB);
#pragma unroll
            for (int mi = 0; mi < 4; mi++) ldm4(a[mi], sA + aoff + mi * 16 * ROWB);
#pragma unroll
            for (int mi = 0; mi < 4; mi++)
#pragma unroll
                for (int fi = 0; fi < 4; fi++)
                    mma16816(acc[mi][fi], a[mi], &bfr[fi >> 1][(fi & 1) * 2]);
        }
        __syncthreads();
    }
}

// plain GEMM -> fp32 C (+bias), used for itW and w2
__global__ __launch_bounds__(512, 1) void mma_gemm_f(
    const __half* __restrict__ A, int lda, const __half* __restrict__ B,
    const float* __restrict__ bias, float* __restrict__ C, int ldc, int M, int K)
{
    extern __shared__ char smem[];
    const uint32_t sbase = s2u(smem);
    const int tid = threadIdx.x, w = tid >> 5, lane = tid & 31;
    const int bm = blockIdx.y * 128, bn = blockIdx.x * 256;
    const int m0 = (w & 1) * 64, n0w = (w >> 1) * 32;
    float acc[4][4][4];
    gemm_main(acc, A, lda, B, M, K, bm, bn, sbase, tid, m0, n0w, lane);
    int tq = lane >> 2, tr = lane & 3;
#pragma unroll
    for (int mi = 0; mi < 4; mi++)
#pragma unroll
        for (int fi = 0; fi < 4; fi++) {
            int col = bn + n0w + fi * 8 + tr * 2;
            float b0 = bias[col], b1 = bias[col + 1];
#pragma unroll
            for (int half = 0; half < 2; half++) {
                int row = bm + m0 + mi * 16 + tq + half * 8;
                if (row >= M) continue;
                *(float2*)(C + (size_t)row * ldc + col) =
                    make_float2(acc[mi][fi][half * 2 + 0] + b0,
                                acc[mi][fi][half * 2 + 1] + b1);
            }
        }
}

// fused conv/score + w1 GEMM: blockIdx.x in [0,3] = w1 tiles, ==4 = conv+score
__global__ __launch_bounds__(512, 1) void mma_gemm_fused(
    const float* __restrict__ convb, const float* __restrict__ scW,
    const float* __restrict__ scb,   const float* __restrict__ w1b,
    int mxslot)
{
    extern __shared__ char smem[];
    const uint32_t sbase = s2u(smem);
    const int tid = threadIdx.x, w = tid >> 5, lane = tid & 31;
    const int bm = blockIdx.y * 128;
    const int m0 = (w & 1) * 64, n0w = (w >> 1) * 32;
    const bool isConv = (blockIdx.x == 4);
    const int bn = isConv ? 0 : blockIdx.x * 256;
    const __half* A  = isConv ? g_flat : g_cc;
    const __half* B  = isConv ? g_convWt : g_w1Wt;
    const int lda = isConv ? WD : 2 * DIM;
    const int K   = isConv ? WD : 2 * DIM;

    float acc[4][4][4];
    gemm_main(acc, A, lda, B, NTOK, K, bm, bn, sbase, tid, m0, n0w, lane);

    int tq = lane >> 2, tr = lane & 3;
    if (isConv) {
        float* srow = (float*)smem;
        if (tid < 128) srow[tid] = 0.f;
        __syncthreads();
#pragma unroll
        for (int mi = 0; mi < 4; mi++)
#pragma unroll
            for (int half = 0; half < 2; half++) {
                int rl = m0 + mi * 16 + tq + half * 8;
                float s = 0.f;
#pragma unroll
                for (int fi = 0; fi < 4; fi++) {
                    int col = bn + n0w + fi * 8 + tr * 2;
                    float v0 = geluf(acc[mi][fi][half * 2 + 0] + convb[col]);
                    float v1 = geluf(acc[mi][fi][half * 2 + 1] + convb[col + 1]);
                    s += v0 * scW[col] + v1 * scW[col + 1];
                }
                atomicAdd(&srow[rl], s);
            }
        __syncthreads();
        if (tid < 128) {
            int gr = bm + tid;
            if (gr < NTOK) {
                float t = srow[tid] + scb[0];
                g_tsc[gr] = t;
                atomicMax((unsigned int*)&g_mxbuf[mxslot],
                          __float_as_uint(fmaxf(t, 0.f)));
            }
        }
    } else {
#pragma unroll
        for (int mi = 0; mi < 4; mi++)
#pragma unroll
            for (int fi = 0; fi < 4; fi++) {
                int col = bn + n0w + fi * 8 + tr * 2;
                float b0 = w1b[col], b1 = w1b[col + 1];
#pragma unroll
                for (int half = 0; half < 2; half++) {
                    int row = bm + m0 + mi * 16 + tq + half * 8;
                    if (row >= NTOK) continue;
                    float v0 = geluf(acc[mi][fi][half * 2 + 0] + b0);
                    float v1 = geluf(acc[mi][fi][half * 2 + 1] + b1);
                    ushort2 h;
                    h.x = __half_as_ushort(__float2half_rn(v0));
                    h.y = __half_as_ushort(__float2half_rn(v1));
                    *(ushort2*)(g_inter + (size_t)row * HID + col) = h;
                }
            }
    }
}

// ---------------- init kernels ----------------
__global__ void init_masks_kernel(const float* __restrict__ im) {
    int idx = blockIdx.x * blockDim.x + threadIdx.x;
    if (idx < 2) g_mxbuf[idx] = 0.f;
    if (idx >= NTOK) return;
    int b = idx / S2, i = idx % S2;
    auto mask_yes = [&](int j) -> float { return (j <= 1) ? 1.f : im[b * SEQL + (j - 2)]; };
    auto mask_no_end = [&](int j) -> float {
        if (j == 0) return 1.f;
        if (j <= SEQL) return im[b * SEQL + (j - 1)];
        return 0.f;
    };
    float my = mask_yes(i), mne = mask_no_end(i);
    float mask_no_start = (i == 0) ? 0.f : my;
    float last_token = (i < S2 - 1) ? (mask_yes(i + 1) - mask_no_end(i + 1)) : 0.f;
    g_mask[idx] = my;
    g_endm[idx] = my - mne;
    g_selp[idx] = mask_no_start * mne * (1.f - last_token);
    g_active[idx] = my;
    g_ltp[idx] = 0.f;
}

__global__ void init_seqpre_kernel(const float* __restrict__ seqin,
                                   const float* __restrict__ START,
                                   const float* __restrict__ END) {
    int idx = blockIdx.x * blockDim.x + threadIdx.x;
    if (idx >= NTOK * DIM) return;
    int tok = idx / DIM, f = idx % DIM;
    int b = tok / S2, i = tok % S2;
    float base;
    if (i == 0)          base = START[f];
    else if (i <= SEQL)  base = seqin[((size_t)b * SEQL + (i - 1)) * DIM + f];
    else                 base = 0.f;
    float e = g_endm[tok];
    float x = e * END[f] + (1.f - e) * base;
    g_cc[(size_t)tok * (2 * DIM) + f] = __float2half_rn(x);
}

__global__ void ln_init_kernel(const float* __restrict__ lng, const float* __restrict__ lnb) {
    int tok = blockIdx.x, f = threadIdx.x;
    float x = g_convOut[(size_t)tok * DIM + f];
    float mean = blockReduceSum256(x) * (1.f / DIM);
    float d = x - mean;
    float r = rsqrtf(blockReduceSum256(d * d) * (1.f / DIM) + 1e-5f);
    g_seq[(size_t)tok * DIM + f] = (d * r * lng[f] + lnb[f]) * g_mask[tok];
}

__global__ void pack_all(const float* __restrict__ Wit, __half* __restrict__ Tit,
                         const float* __restrict__ Wcv, __half* __restrict__ Tcv,
                         const float* __restrict__ W1,  __half* __restrict__ T1,
                         const float* __restrict__ W2,  __half* __restrict__ T2) {
    int i = blockIdx.x * blockDim.x + threadIdx.x;
    const int n_it = DIM * DIM;
    const int n_cv = DIM * WD;
    const int n_w1 = HID * 2 * DIM;
    const int n_w2 = HID * HID;
    if (i < n_it) {
        int n = i / DIM, k = i % DIM;
        Tit[i] = __float2half_rn(Wit[(size_t)k * DIM + n]);
    } else if (i < n_it + n_cv) {
        int j = i - n_it;
        int n = j / WD, k = j % WD;
        Tcv[j] = __float2half_rn(Wcv[(size_t)k * DIM + n]);
    } else if (i < n_it + n_cv + n_w1) {
        int j = i - n_it - n_cv;
        int n = j / (2 * DIM), k = j % (2 * DIM);
        T1[j] = __float2half_rn(W1[(size_t)k * HID + n]);
    } else {
        int j = i - n_it - n_cv - n_w1;
        if (j >= n_w2) return;
        int n = j / HID, k = j % HID;
        T2[j] = __float2half_rn(W2[(size_t)k * HID + n]);
    }
}

// ---------------- scalar-per-feature scan (4x warps vs float4 version) ----------------
// grid: NB*2*2 blocks of 128 threads. dir 0 = fwd, 1 = bwd; fh = feature half.
// Arithmetic element-wise identical to the float4 version (bit-identical results).
__global__ void scan_kernel(const float* __restrict__ yes_t, const float* __restrict__ no_t) {
    int bid = blockIdx.x;
    int dir = bid & 1;
    int fh  = (bid >> 1) & 1;
    int b   = bid >> 2;
    int f   = fh * 128 + threadIdx.x;
    float yf = yes_t[f], nf = no_t[f];
    if (dir == 0) {
        float l1 = 0.f, l2 = 0.f, lc = 0.f;
        for (int i = 0; i < S2; i++) {
            int tok = b * S2 + i;
            float a = g_active[tok], m = g_mask[tok], lt = g_ltp[tok];
            float w = a * m * m, c = 1.f - a * m + EPSF;
            float sv = g_seq[(size_t)tok * DIM + f];
            float base = sv + lt * yf + (1.f - lt) * nf;
            size_t fl = (size_t)tok * WD;
            g_flat[fl + 0 * DIM + f] = __float2half_rn(l2);
            g_flat[fl + 1 * DIM + f] = __float2half_rn(l1);
            size_t cp = (size_t)tok * 2 * DIM;
            g_cc[cp + f]       = __float2half_rn(lc);
            g_cc[cp + DIM + f] = __float2half_rn(sv);
            float nl2 = w * l1 + c * l2;
            l1 = w * base + c * l1;
            lc = w * sv + c * lc;
            l2 = nl2;
        }
    } else {
        float r1 = 0.f, r2 = 0.f;
        for (int i = S2 - 1; i >= 0; i--) {
            int tok = b * S2 + i;
            float a = g_active[tok], m = g_mask[tok], lt = g_ltp[tok];
            float w = a * m * m, c = 1.f - a * m + EPSF;
            float sv = g_seq[(size_t)tok * DIM + f];
            float base = sv + lt * yf + (1.f - lt) * nf;
            size_t fl = (size_t)tok * WD;
            g_flat[fl + 2 * DIM + f] = __float2half_rn(base);
            g_flat[fl + 3 * DIM + f] = __float2half_rn(r1);
            g_flat[fl + 4 * DIM + f] = __float2half_rn(r2);
            float nr2 = w * r1 + c * r2;
            r1 = w * base + c * r1;
            r2 = nr2;
        }
    }
}

// ---------------- merged combine + deact kernel ----------------
__global__ void combine_deact_kernel(const float* __restrict__ lng,
                                     const float* __restrict__ lnb,
                                     int mxslot, float* __restrict__ out) {
    if (blockIdx.x < NTOK) {
        int tok = blockIdx.x, f = threadIdx.x;
        const float* ct = g_contents + (size_t)tok * HID;
        size_t cp = (size_t)tok * 2 * DIM;
        float lc = __half2float(g_cc[cp + f]);
        float sv = g_seq[(size_t)tok * DIM + f];
        float g0 = 1.f / (1.f + expf(-ct[0 * DIM + f]));
        float g1 = 1.f / (1.f + expf(-ct[1 * DIM + f]));
        float g2 = 1.f / (1.f + expf(-ct[2 * DIM + f]));
        float y = g0 * lc + g1 * sv + g2 * ct[3 * DIM + f];
        float mean = blockReduceSum256(y) * (1.f / DIM);
        float d = y - mean;
        float r = rsqrtf(blockReduceSum256(d * d) * (1.f / DIM) + 1e-5f);
        float comp = d * r * lng[f] + lnb[f];
        float mx = g_mxbuf[mxslot];
        float et = expf(g_tsc[tok] - mx) * g_selp[tok];
        float tp = et / (et + expf(-mx) + EPSF);
        float res = (tp * comp + (1.f - tp) * sv) * g_mask[tok];
        g_seq[(size_t)tok * DIM + f] = res;
        if (out) out[(size_t)tok * DIM + f] = res;
    } else {
        __shared__ float s_a[S2], s_m[S2], s_tp[S2];
        int b = blockIdx.x - NTOK;
        float mx = g_mxbuf[mxslot];
        if (b == 0 && threadIdx.x == 0) g_mxbuf[mxslot ^ 1] = 0.f;
        float en = expf(-mx);
        for (int i = threadIdx.x; i < S2; i += blockDim.x) {
            int tok = b * S2 + i;
            s_a[i] = g_active[tok]; s_m[i] = g_mask[tok];
            float et = expf(g_tsc[tok] - mx) * g_selp[tok];
            s_tp[i] = et / (et + en + EPSF);
        }
        __syncthreads();
        if (threadIdx.x == 0) {
            float dacc = 0.f;
            for (int j = S2 - 1; j >= 0; j--) {
                float a = s_a[j], m = s_m[j], tp = s_tp[j];
                float de = a * m * m * dacc;
                s_a[j] = fminf(fmaxf(a * (1.f - de), 0.f), 1.f) * m;
                dacc = tp + (1.f - a * m + EPSF) * dacc;
            }
        }
        __syncthreads();
        for (int i = threadIdx.x; i < S2; i += blockDim.x) {
            int tok = b * S2 + i;
            g_active[tok] = s_a[i];
            g_ltp[tok]    = s_tp[i];
        }
    }
}

// ---------------- launch ----------------
extern "C" void kernel_launch(void* const* d_in, const int* in_sizes, int n_in,
                              void* d_out, int out_size) {
    const float* sequence   = (const float*)d_in[0];
    const float* input_mask = (const float*)d_in[1];
    const float* START = (const float*)d_in[2];
    const float* END   = (const float*)d_in[3];
    const float* yes_t = (const float*)d_in[4];
    const float* no_t  = (const float*)d_in[5];
    const float* convW = (const float*)d_in[6];
    const float* convb = (const float*)d_in[7];
    const float* scW   = (const float*)d_in[8];
    const float* scb   = (const float*)d_in[9];
    const float* itW   = (const float*)d_in[10];
    const float* itb   = (const float*)d_in[11];
    const float* w1W   = (const float*)d_in[12];
    const float* w1b   = (const float*)d_in[13];
    const float* w2W   = (const float*)d_in[14];
    const float* w2b   = (const float*)d_in[15];
    const float* lng   = (const float*)d_in[16];
    const float* lnb   = (const float*)d_in[17];
    float* out = (float*)d_out;

    __half *p_cc, *p_inter, *p_convWt, *p_w1Wt, *p_w2Wt, *p_itWt;
    float *p_contents, *p_convOut;
    cudaGetSymbolAddress((void**)&p_cc, g_cc);
    cudaGetSymbolAddress((void**)&p_inter, g_inter);
    cudaGetSymbolAddress((void**)&p_contents, g_contents);
    cudaGetSymbolAddress((void**)&p_convOut, g_convOut);
    cudaGetSymbolAddress((void**)&p_convWt, g_convWt);
    cudaGetSymbolAddress((void**)&p_w1Wt, g_w1Wt);
    cudaGetSymbolAddress((void**)&p_w2Wt, g_w2Wt);
    cudaGetSymbolAddress((void**)&p_itWt, g_itWt);

    cudaFuncSetAttribute(mma_gemm_f, cudaFuncAttributeMaxDynamicSharedMemorySize, SMEMB);
    cudaFuncSetAttribute(mma_gemm_fused, cudaFuncAttributeMaxDynamicSharedMemorySize, SMEMB);

    const int THR = 256;
    const int GM = (NTOK + 127) / 128;   // 129
    const int PACK_N = DIM * DIM + DIM * WD + HID * 2 * DIM + HID * HID;

    init_masks_kernel<<<(NTOK + THR - 1) / THR, THR>>>(input_mask);
    init_seqpre_kernel<<<(NTOK * DIM + THR - 1) / THR, THR>>>(sequence, START, END);
    pack_all<<<(PACK_N + THR - 1) / THR, THR>>>(itW, p_itWt, convW, p_convWt,
                                                w1W, p_w1Wt, w2W, p_w2Wt);

    mma_gemm_f<<<dim3(1, GM), 512, SMEMB>>>(p_cc, 2 * DIM, p_itWt, itb,
                                            p_convOut, DIM, NTOK, DIM);
    ln_init_kernel<<<NTOK, DIM>>>(lng, lnb);

    for (int s = 0; s < NSTEPS; s++) {
        int slot = s & 1;
        scan_kernel<<<NB * 4, 128>>>(yes_t, no_t);
        mma_gemm_fused<<<dim3(5, GM), 512, SMEMB>>>(convb, scW, scb, w1b, slot);
        mma_gemm_f<<<dim3(4, GM), 512, SMEMB>>>(p_inter, HID, p_w2Wt, w2b,
                                                p_contents, HID, NTOK, HID);
        combine_deact_kernel<<<NTOK + NB, 256>>>(lng, lnb, slot,
                                                 (s == NSTEPS - 1) ? out : nullptr);
    }
}

// round 15
// speedup vs baseline: 1.4128x; 1.0885x over previous
#include <cuda_runtime.h>
#include <cuda_fp16.h>
#include <math.h>
#include <stdint.h>

#define NB   32
#define SEQL 512
#define DIM  256
#define S2   514
#define NTOK (NB * S2)
#define HID  1024
#define WD   1280
#define NSTEPS 6
#define EPSF 1e-9f

static __device__ __align__(256) __half g_flat[NTOK * WD];
static __device__ __align__(256) __half g_cc[NTOK * 2 * DIM];
static __device__ __align__(256) __half g_inter[NTOK * HID];
static __device__ __align__(256) float g_contents[NTOK * HID];
static __device__ __align__(256) float g_convOut[NTOK * DIM];
static __device__ __align__(256) float g_seq[NTOK * DIM];
static __device__ float g_tsc[NTOK], g_ltp[NTOK];
static __device__ float g_active[NTOK], g_mask[NTOK], g_selp[NTOK], g_endm[NTOK];
static __device__ float g_mxbuf[2];
static __device__ __align__(256) __half g_convWt[DIM * WD];
static __device__ __align__(256) __half g_w1Wt[HID * 2 * DIM];
static __device__ __align__(256) __half g_w2Wt[HID * HID];
static __device__ __align__(256) __half g_itWt[DIM * DIM];

__device__ __forceinline__ float geluf(float x) {
    float x3 = x * x * x;
    return 0.5f * x * (1.f + tanhf(0.7978845608028654f * (x + 0.044715f * x3)));
}
__device__ __forceinline__ float blockReduceSum256(float v) {
    __shared__ float sh[33];
    int lane = threadIdx.x & 31, wid = threadIdx.x >> 5;
#pragma unroll
    for (int o = 16; o; o >>= 1) v += __shfl_down_sync(0xffffffffu, v, o);
    __syncthreads();
    if (lane == 0) sh[wid] = v;
    __syncthreads();
    if (wid == 0) {
        float t = (lane < 8) ? sh[lane] : 0.f;
#pragma unroll
        for (int o = 16; o; o >>= 1) t += __shfl_down_sync(0xffffffffu, t, o);
        if (lane == 0) sh[32] = t;
    }
    __syncthreads();
    return sh[32];
}

// ---------------- mma.sync helpers ----------------
__device__ __forceinline__ uint32_t s2u(const void* p) { return (uint32_t)__cvta_generic_to_shared(p); }
__device__ __forceinline__ void ldm4(uint32_t* r, uint32_t a) {
    asm volatile("ldmatrix.sync.aligned.m8n8.x4.shared.b16 {%0,%1,%2,%3}, [%4];"
                 : "=r"(r[0]), "=r"(r[1]), "=r"(r[2]), "=r"(r[3]) : "r"(a));
}
__device__ __forceinline__ void mma16816(float* c, const uint32_t* a, const uint32_t* b) {
    asm volatile("mma.sync.aligned.m16n8k16.row.col.f32.f16.f16.f32 "
                 "{%0,%1,%2,%3},{%4,%5,%6,%7},{%8,%9},{%0,%1,%2,%3};"
                 : "+f"(c[0]), "+f"(c[1]), "+f"(c[2]), "+f"(c[3])
                 : "r"(a[0]), "r"(a[1]), "r"(a[2]), "r"(a[3]), "r"(b[0]), "r"(b[1]));
}
__device__ __forceinline__ void cpasync16(uint32_t dst, const void* src, int srcsize) {
    asm volatile("cp.async.cg.shared.global [%0], [%1], 16, %2;"
                 :: "r"(dst), "l"(src), "r"(srcsize) : "memory");
}

#define ROWB 144

// ============ small-tile GEMM: 128x128 CTA, 256 threads, 2 CTAs/SM ============
#define STG_S 36864
#define SMEM_S (3 * STG_S)     // 110592
template <int ACT, int OUTP>
__global__ __launch_bounds__(256, 2) void mma_gemm_s(
    const __half* __restrict__ A, int lda, const __half* __restrict__ B,
    const float* __restrict__ bias, void* __restrict__ C, int ldc, int M, int K)
{
    extern __shared__ char smem[];
    const uint32_t sbase = s2u(smem);
    const int tid = threadIdx.x, w = tid >> 5, lane = tid & 31;
    const int bm = blockIdx.y * 128, bn = blockIdx.x * 128;
    const int m0 = (w & 1) * 64, n0w = (w >> 1) * 32;
    const int NK = K >> 6;

    float acc[4][4][4];
#pragma unroll
    for (int i = 0; i < 4; i++)
#pragma unroll
        for (int j = 0; j < 4; j++)
#pragma unroll
            for (int e = 0; e < 4; e++) acc[i][j][e] = 0.f;

    auto fill = [&](int st, int kt) {
        int k0 = kt << 6;
#pragma unroll
        for (int q = 0; q < 8; q++) {
            int u = tid + q * 256;     // 2048 units of 16B
            const __half* src;
            uint32_t dst;
            int sz = 16;
            if (u < 1024) {
                int r = u >> 3, c = u & 7;
                int gr = bm + r;
                if (gr >= M) { gr = 0; sz = 0; }
                src = A + (size_t)gr * lda + k0 + c * 8;
                dst = sbase + st * STG_S + r * ROWB + c * 16;
            } else {
                int v = u - 1024;
                int r = v >> 3, c = v & 7;
                src = B + (size_t)(bn + r) * K + k0 + c * 8;
                dst = sbase + st * STG_S + 18432 + r * ROWB + c * 16;
            }
            cpasync16(dst, src, sz);
        }
        asm volatile("cp.async.commit_group;" ::: "memory");
    };

    fill(0, 0);
    fill(1, 1);
    for (int kt = 0; kt < NK; kt++) {
        if (kt + 2 < NK) {
            fill((kt + 2) % 3, kt + 2);
            asm volatile("cp.async.wait_group 2;" ::: "memory");
        } else if (kt + 1 < NK) {
            asm volatile("cp.async.wait_group 1;" ::: "memory");
        } else {
            asm volatile("cp.async.wait_group 0;" ::: "memory");
        }
        __syncthreads();
        const uint32_t sA = sbase + (kt % 3) * STG_S;
        const uint32_t sB = sA + 18432;
#pragma unroll
        for (int kh = 0; kh < 4; kh++) {
            uint32_t a[4][4], bfr[2][4];
            int aoff = (m0 + (lane & 15)) * ROWB + kh * 32 + (lane >> 4) * 16;
            int boff = (n0w + ((lane & 7) | ((lane >> 1) & 8))) * ROWB
                       + kh * 32 + ((lane >> 3) & 1) * 16;
#pragma unroll
            for (int nt = 0; nt < 2; nt++)
                ldm4(bfr[nt], sB + boff + nt * 16 * ROWB);
#pragma unroll
            for (int mi = 0; mi < 4; mi++) ldm4(a[mi], sA + aoff + mi * 16 * ROWB);
#pragma unroll
            for (int mi = 0; mi < 4; mi++)
#pragma unroll
                for (int fi = 0; fi < 4; fi++)
                    mma16816(acc[mi][fi], a[mi], &bfr[fi >> 1][(fi & 1) * 2]);
        }
        __syncthreads();
    }

    int tq = lane >> 2, tr = lane & 3;
#pragma unroll
    for (int mi = 0; mi < 4; mi++)
#pragma unroll
        for (int fi = 0; fi < 4; fi++) {
            int col = bn + n0w + fi * 8 + tr * 2;
            float b0 = bias[col], b1 = bias[col + 1];
#pragma unroll
            for (int half = 0; half < 2; half++) {
                int row = bm + m0 + mi * 16 + tq + half * 8;
                if (row >= M) continue;
                float v0 = acc[mi][fi][half * 2 + 0] + b0;
                float v1 = acc[mi][fi][half * 2 + 1] + b1;
                if (ACT) { v0 = geluf(v0); v1 = geluf(v1); }
                if (OUTP) {
                    ushort2 h;
                    h.x = __half_as_ushort(__float2half_rn(v0));
                    h.y = __half_as_ushort(__float2half_rn(v1));
                    *(ushort2*)((__half*)C + (size_t)row * ldc + col) = h;
                } else {
                    *(float2*)((float*)C + (size_t)row * ldc + col) = make_float2(v0, v1);
                }
            }
        }
}

// ============ conv+score GEMM: 128x256 CTA, 512 threads (proven shape) ============
#define STG_B 55296
#define SMEM_B (3 * STG_B)     // 165888
__global__ __launch_bounds__(512, 1) void mma_gemm_score(
    const float* __restrict__ convb, const float* __restrict__ scW,
    const float* __restrict__ scb, int mxslot)
{
    extern __shared__ char smem[];
    const uint32_t sbase = s2u(smem);
    const int tid = threadIdx.x, w = tid >> 5, lane = tid & 31;
    const int bm = blockIdx.y * 128;
    const int m0 = (w & 1) * 64, n0w = (w >> 1) * 32;
    const int K = WD, NK = K >> 6;
    const __half* A = g_flat;
    const __half* B = g_convWt;

    float acc[4][4][4];
#pragma unroll
    for (int i = 0; i < 4; i++)
#pragma unroll
        for (int j = 0; j < 4; j++)
#pragma unroll
            for (int e = 0; e < 4; e++) acc[i][j][e] = 0.f;

    auto fill = [&](int st, int kt) {
        int k0 = kt << 6;
#pragma unroll
        for (int q = 0; q < 6; q++) {
            int u = tid + q * 512;
            const __half* src;
            uint32_t dst;
            int sz = 16;
            if (u < 1024) {
                int r = u >> 3, c = u & 7;
                int gr = bm + r;
                if (gr >= NTOK) { gr = 0; sz = 0; }
                src = A + (size_t)gr * WD + k0 + c * 8;
                dst = sbase + st * STG_B + r * ROWB + c * 16;
            } else {
                int v = u - 1024;
                int r = (v >> 3) & 255, c = v & 7;
                src = B + (size_t)r * K + k0 + c * 8;
                dst = sbase + st * STG_B + 18432 + r * ROWB + c * 16;
            }
            cpasync16(dst, src, sz);
        }
        asm volatile("cp.async.commit_group;" ::: "memory");
    };

    fill(0, 0);
    fill(1, 1);
    for (int kt = 0; kt < NK; kt++) {
        if (kt + 2 < NK) {
            fill((kt + 2) % 3, kt + 2);
            asm volatile("cp.async.wait_group 2;" ::: "memory");
        } else if (kt + 1 < NK) {
            asm volatile("cp.async.wait_group 1;" ::: "memory");
        } else {
            asm volatile("cp.async.wait_group 0;" ::: "memory");
        }
        __syncthreads();
        const uint32_t sA = sbase + (kt % 3) * STG_B;
        const uint32_t sB = sA + 18432;
#pragma unroll
        for (int kh = 0; kh < 4; kh++) {
            uint32_t a[4][4], bfr[2][4];
            int aoff = (m0 + (lane & 15)) * ROWB + kh * 32 + (lane >> 4) * 16;
            int boff = (n0w + ((lane & 7) | ((lane >> 1) & 8))) * ROWB
                       + kh * 32 + ((lane >> 3) & 1) * 16;
#pragma unroll
            for (int nt = 0; nt < 2; nt++)
                ldm4(bfr[nt], sB + boff + nt * 16 * ROWB);
#pragma unroll
            for (int mi = 0; mi < 4; mi++) ldm4(a[mi], sA + aoff + mi * 16 * ROWB);
#pragma unroll
            for (int mi = 0; mi < 4; mi++)
#pragma unroll
                for (int fi = 0; fi < 4; fi++)
                    mma16816(acc[mi][fi], a[mi], &bfr[fi >> 1][(fi & 1) * 2]);
        }
        __syncthreads();
    }

    int tq = lane >> 2, tr = lane & 3;
    float* srow = (float*)smem;
    if (tid < 128) srow[tid] = 0.f;
    __syncthreads();
#pragma unroll
    for (int mi = 0; mi < 4; mi++)
#pragma unroll
        for (int half = 0; half < 2; half++) {
            int rl = m0 + mi * 16 + tq + half * 8;
            float s = 0.f;
#pragma unroll
            for (int fi = 0; fi < 4; fi++) {
                int col = n0w + fi * 8 + tr * 2;
                float v0 = geluf(acc[mi][fi][half * 2 + 0] + convb[col]);
                float v1 = geluf(acc[mi][fi][half * 2 + 1] + convb[col + 1]);
                s += v0 * scW[col] + v1 * scW[col + 1];
            }
            atomicAdd(&srow[rl], s);
        }
    __syncthreads();
    if (tid < 128) {
        int gr = bm + tid;
        if (gr < NTOK) {
            float t = srow[tid] + scb[0];
            g_tsc[gr] = t;
            atomicMax((unsigned int*)&g_mxbuf[mxslot], __float_as_uint(fmaxf(t, 0.f)));
        }
    }
}

// ---------------- init kernels ----------------
__global__ void init_masks_kernel(const float* __restrict__ im) {
    int idx = blockIdx.x * blockDim.x + threadIdx.x;
    if (idx < 2) g_mxbuf[idx] = 0.f;
    if (idx >= NTOK) return;
    int b = idx / S2, i = idx % S2;
    auto mask_yes = [&](int j) -> float { return (j <= 1) ? 1.f : im[b * SEQL + (j - 2)]; };
    auto mask_no_end = [&](int j) -> float {
        if (j == 0) return 1.f;
        if (j <= SEQL) return im[b * SEQL + (j - 1)];
        return 0.f;
    };
    float my = mask_yes(i), mne = mask_no_end(i);
    float mask_no_start = (i == 0) ? 0.f : my;
    float last_token = (i < S2 - 1) ? (mask_yes(i + 1) - mask_no_end(i + 1)) : 0.f;
    g_mask[idx] = my;
    g_endm[idx] = my - mne;
    g_selp[idx] = mask_no_start * mne * (1.f - last_token);
    g_active[idx] = my;
    g_ltp[idx] = 0.f;
}

__global__ void init_seqpre_kernel(const float* __restrict__ seqin,
                                   const float* __restrict__ START,
                                   const float* __restrict__ END) {
    int idx = blockIdx.x * blockDim.x + threadIdx.x;
    if (idx >= NTOK * DIM) return;
    int tok = idx / DIM, f = idx % DIM;
    int b = tok / S2, i = tok % S2;
    float base;
    if (i == 0)          base = START[f];
    else if (i <= SEQL)  base = seqin[((size_t)b * SEQL + (i - 1)) * DIM + f];
    else                 base = 0.f;
    float e = g_endm[tok];
    float x = e * END[f] + (1.f - e) * base;
    g_cc[(size_t)tok * (2 * DIM) + f] = __float2half_rn(x);
}

__global__ void ln_init_kernel(const float* __restrict__ lng, const float* __restrict__ lnb) {
    int tok = blockIdx.x, f = threadIdx.x;
    float x = g_convOut[(size_t)tok * DIM + f];
    float mean = blockReduceSum256(x) * (1.f / DIM);
    float d = x - mean;
    float r = rsqrtf(blockReduceSum256(d * d) * (1.f / DIM) + 1e-5f);
    g_seq[(size_t)tok * DIM + f] = (d * r * lng[f] + lnb[f]) * g_mask[tok];
}

__global__ void pack_all(const float* __restrict__ Wit, __half* __restrict__ Tit,
                         const float* __restrict__ Wcv, __half* __restrict__ Tcv,
                         const float* __restrict__ W1,  __half* __restrict__ T1,
                         const float* __restrict__ W2,  __half* __restrict__ T2) {
    int i = blockIdx.x * blockDim.x + threadIdx.x;
    const int n_it = DIM * DIM;
    const int n_cv = DIM * WD;
    const int n_w1 = HID * 2 * DIM;
    const int n_w2 = HID * HID;
    if (i < n_it) {
        int n = i / DIM, k = i % DIM;
        Tit[i] = __float2half_rn(Wit[(size_t)k * DIM + n]);
    } else if (i < n_it + n_cv) {
        int j = i - n_it;
        int n = j / WD, k = j % WD;
        Tcv[j] = __float2half_rn(Wcv[(size_t)k * DIM + n]);
    } else if (i < n_it + n_cv + n_w1) {
        int j = i - n_it - n_cv;
        int n = j / (2 * DIM), k = j % (2 * DIM);
        T1[j] = __float2half_rn(W1[(size_t)k * HID + n]);
    } else {
        int j = i - n_it - n_cv - n_w1;
        if (j >= n_w2) return;
        int n = j / HID, k = j % HID;
        T2[j] = __float2half_rn(W2[(size_t)k * HID + n]);
    }
}

// ---------------- scalar-per-feature scan ----------------
__global__ void scan_kernel(const float* __restrict__ yes_t, const float* __restrict__ no_t) {
    int bid = blockIdx.x;
    int dir = bid & 1;
    int fh  = (bid >> 1) & 1;
    int b   = bid >> 2;
    int f   = fh * 128 + threadIdx.x;
    float yf = yes_t[f], nf = no_t[f];
    if (dir == 0) {
        float l1 = 0.f, l2 = 0.f, lc = 0.f;
        for (int i = 0; i < S2; i++) {
            int tok = b * S2 + i;
            float a = g_active[tok], m = g_mask[tok], lt = g_ltp[tok];
            float w = a * m * m, c = 1.f - a * m + EPSF;
            float sv = g_seq[(size_t)tok * DIM + f];
            float base = sv + lt * yf + (1.f - lt) * nf;
            size_t fl = (size_t)tok * WD;
            g_flat[fl + 0 * DIM + f] = __float2half_rn(l2);
            g_flat[fl + 1 * DIM + f] = __float2half_rn(l1);
            size_t cp = (size_t)tok * 2 * DIM;
            g_cc[cp + f]       = __float2half_rn(lc);
            g_cc[cp + DIM + f] = __float2half_rn(sv);
            float nl2 = w * l1 + c * l2;
            l1 = w * base + c * l1;
            lc = w * sv + c * lc;
            l2 = nl2;
        }
    } else {
        float r1 = 0.f, r2 = 0.f;
        for (int i = S2 - 1; i >= 0; i--) {
            int tok = b * S2 + i;
            float a = g_active[tok], m = g_mask[tok], lt = g_ltp[tok];
            float w = a * m * m, c = 1.f - a * m + EPSF;
            float sv = g_seq[(size_t)tok * DIM + f];
            float base = sv + lt * yf + (1.f - lt) * nf;
            size_t fl = (size_t)tok * WD;
            g_flat[fl + 2 * DIM + f] = __float2half_rn(base);
            g_flat[fl + 3 * DIM + f] = __float2half_rn(r1);
            g_flat[fl + 4 * DIM + f] = __float2half_rn(r2);
            float nr2 = w * r1 + c * r2;
            r1 = w * base + c * r1;
            r2 = nr2;
        }
    }
}

// ---------------- merged combine + deact kernel ----------------
__global__ void combine_deact_kernel(const float* __restrict__ lng,
                                     const float* __restrict__ lnb,
                                     int mxslot, float* __restrict__ out) {
    if (blockIdx.x < NTOK) {
        int tok = blockIdx.x, f = threadIdx.x;
        const float* ct = g_contents + (size_t)tok * HID;
        size_t cp = (size_t)tok * 2 * DIM;
        float lc = __half2float(g_cc[cp + f]);
        float sv = g_seq[(size_t)tok * DIM + f];
        float g0 = 1.f / (1.f + expf(-ct[0 * DIM + f]));
        float g1 = 1.f / (1.f + expf(-ct[1 * DIM + f]));
        float g2 = 1.f / (1.f + expf(-ct[2 * DIM + f]));
        float y = g0 * lc + g1 * sv + g2 * ct[3 * DIM + f];
        float mean = blockReduceSum256(y) * (1.f / DIM);
        float d = y - mean;
        float r = rsqrtf(blockReduceSum256(d * d) * (1.f / DIM) + 1e-5f);
        float comp = d * r * lng[f] + lnb[f];
        float mx = g_mxbuf[mxslot];
        float et = expf(g_tsc[tok] - mx) * g_selp[tok];
        float tp = et / (et + expf(-mx) + EPSF);
        float res = (tp * comp + (1.f - tp) * sv) * g_mask[tok];
        g_seq[(size_t)tok * DIM + f] = res;
        if (out) out[(size_t)tok * DIM + f] = res;
    } else {
        __shared__ float s_a[S2], s_m[S2], s_tp[S2];
        int b = blockIdx.x - NTOK;
        float mx = g_mxbuf[mxslot];
        if (b == 0 && threadIdx.x == 0) g_mxbuf[mxslot ^ 1] = 0.f;
        float en = expf(-mx);
        for (int i = threadIdx.x; i < S2; i += blockDim.x) {
            int tok = b * S2 + i;
            s_a[i] = g_active[tok]; s_m[i] = g_mask[tok];
            float et = expf(g_tsc[tok] - mx) * g_selp[tok];
            s_tp[i] = et / (et + en + EPSF);
        }
        __syncthreads();
        if (threadIdx.x == 0) {
            float dacc = 0.f;
            for (int j = S2 - 1; j >= 0; j--) {
                float a = s_a[j], m = s_m[j], tp = s_tp[j];
                float de = a * m * m * dacc;
                s_a[j] = fminf(fmaxf(a * (1.f - de), 0.f), 1.f) * m;
                dacc = tp + (1.f - a * m + EPSF) * dacc;
            }
        }
        __syncthreads();
        for (int i = threadIdx.x; i < S2; i += blockDim.x) {
            int tok = b * S2 + i;
            g_active[tok] = s_a[i];
            g_ltp[tok]    = s_tp[i];
        }
    }
}

// ---------------- launch ----------------
extern "C" void kernel_launch(void* const* d_in, const int* in_sizes, int n_in,
                              void* d_out, int out_size) {
    const float* sequence   = (const float*)d_in[0];
    const float* input_mask = (const float*)d_in[1];
    const float* START = (const float*)d_in[2];
    const float* END   = (const float*)d_in[3];
    const float* yes_t = (const float*)d_in[4];
    const float* no_t  = (const float*)d_in[5];
    const float* convW = (const float*)d_in[6];
    const float* convb = (const float*)d_in[7];
    const float* scW   = (const float*)d_in[8];
    const float* scb   = (const float*)d_in[9];
    const float* itW   = (const float*)d_in[10];
    const float* itb   = (const float*)d_in[11];
    const float* w1W   = (const float*)d_in[12];
    const float* w1b   = (const float*)d_in[13];
    const float* w2W   = (const float*)d_in[14];
    const float* w2b   = (const float*)d_in[15];
    const float* lng   = (const float*)d_in[16];
    const float* lnb   = (const float*)d_in[17];
    float* out = (float*)d_out;

    __half *p_cc, *p_inter, *p_convWt, *p_w1Wt, *p_w2Wt, *p_itWt;
    float *p_contents, *p_convOut;
    cudaGetSymbolAddress((void**)&p_cc, g_cc);
    cudaGetSymbolAddress((void**)&p_inter, g_inter);
    cudaGetSymbolAddress((void**)&p_contents, g_contents);
    cudaGetSymbolAddress((void**)&p_convOut, g_convOut);
    cudaGetSymbolAddress((void**)&p_convWt, g_convWt);
    cudaGetSymbolAddress((void**)&p_w1Wt, g_w1Wt);
    cudaGetSymbolAddress((void**)&p_w2Wt, g_w2Wt);
    cudaGetSymbolAddress((void**)&p_itWt, g_itWt);

    cudaFuncSetAttribute(mma_gemm_s<0,0>, cudaFuncAttributeMaxDynamicSharedMemorySize, SMEM_S);
    cudaFuncSetAttribute(mma_gemm_s<1,1>, cudaFuncAttributeMaxDynamicSharedMemorySize, SMEM_S);
    cudaFuncSetAttribute(mma_gemm_score, cudaFuncAttributeMaxDynamicSharedMemorySize, SMEM_B);

    const int THR = 256;
    const int GM = (NTOK + 127) / 128;   // 129
    const int PACK_N = DIM * DIM + DIM * WD + HID * 2 * DIM + HID * HID;

    init_masks_kernel<<<(NTOK + THR - 1) / THR, THR>>>(input_mask);
    init_seqpre_kernel<<<(NTOK * DIM + THR - 1) / THR, THR>>>(sequence, START, END);
    pack_all<<<(PACK_N + THR - 1) / THR, THR>>>(itW, p_itWt, convW, p_convWt,
                                                w1W, p_w1Wt, w2W, p_w2Wt);

    mma_gemm_s<0,0><<<dim3(2, GM), 256, SMEM_S>>>(p_cc, 2 * DIM, p_itWt, itb,
                                                  p_convOut, DIM, NTOK, DIM);
    ln_init_kernel<<<NTOK, DIM>>>(lng, lnb);

    for (int s = 0; s < NSTEPS; s++) {
        int slot = s & 1;
        scan_kernel<<<NB * 4, 128>>>(yes_t, no_t);
        mma_gemm_score<<<dim3(1, GM), 512, SMEM_B>>>(convb, scW, scb, slot);
        mma_gemm_s<1,1><<<dim3(8, GM), 256, SMEM_S>>>(p_cc, 2 * DIM, p_w1Wt, w1b,
                                                      p_inter, HID, NTOK, 2 * DIM);
        mma_gemm_s<0,0><<<dim3(8, GM), 256, SMEM_S>>>(p_inter, HID, p_w2Wt, w2b,
                                                      p_contents, HID, NTOK, HID);
        combine_deact_kernel<<<NTOK + NB, 256>>>(lng, lnb, slot,
                                                 (s == NSTEPS - 1) ? out : nullptr);
    }
}